// round 10
// baseline (speedup 1.0000x reference)
#include <cuda_runtime.h>
#include <cuda_fp16.h>

// Problem dims
#define TT 512
#define BB 256
#define SS 64
#define HH 128
#define NROW (TT*BB)          // 131072

// ---------------- scratch (device globals; no allocation allowed) ----------------
__device__ __half g_f2h[(size_t)2 * NROW * HH];      // post-MLP features fp16 (67MB)
__device__ __half g_hh [(size_t)2 * NROW * HH];      // LSTM hidden outputs fp16 (67MB)

// ---------------- helpers ----------------
__device__ __forceinline__ float tanh_t(float x) {
    float y; asm("tanh.approx.f32 %0, %1;" : "=f"(y) : "f"(x)); return y;
}
__device__ __forceinline__ float sig_t(float x) {
    return fmaf(tanh_t(x * 0.5f), 0.5f, 0.5f);
}
__device__ __forceinline__ void mma16816(float* c, const unsigned* a, const unsigned* b) {
    asm volatile(
        "mma.sync.aligned.m16n8k16.row.col.f32.f16.f16.f32 "
        "{%0,%1,%2,%3}, {%4,%5,%6,%7}, {%8,%9}, {%0,%1,%2,%3};\n"
        : "+f"(c[0]), "+f"(c[1]), "+f"(c[2]), "+f"(c[3])
        : "r"(a[0]), "r"(a[1]), "r"(a[2]), "r"(a[3]), "r"(b[0]), "r"(b[1]));
}
__device__ __forceinline__ void ldsm4(unsigned* d, const __half* p) {
    unsigned addr = (unsigned)__cvta_generic_to_shared((void*)p);
    asm volatile("ldmatrix.sync.aligned.m8n8.x4.shared.b16 {%0,%1,%2,%3}, [%4];\n"
                 : "=r"(d[0]), "=r"(d[1]), "=r"(d[2]), "=r"(d[3]) : "r"(addr));
}
__device__ __forceinline__ unsigned smem_u32(const void* p) {
    return (unsigned)__cvta_generic_to_shared((void*)p);
}
__device__ __forceinline__ void cpa16(void* smem_dst, const void* gsrc) {
    unsigned s = smem_u32(smem_dst);
    asm volatile("cp.async.cg.shared.global [%0], [%1], 16;" :: "r"(s), "l"(gsrc));
}
#define CP_COMMIT asm volatile("cp.async.commit_group;" ::: "memory")
#define CP_WAIT0  asm volatile("cp.async.wait_group 0;" ::: "memory")
#define CP_WAIT1  asm volatile("cp.async.wait_group 1;" ::: "memory")

__device__ __forceinline__ unsigned mapa_u32(unsigned addr, unsigned rank) {
    unsigned r;
    asm("mapa.shared::cluster.u32 %0, %1, %2;" : "=r"(r) : "r"(addr), "r"(rank));
    return r;
}
__device__ __forceinline__ void mbar_wait_acq_cluster(unsigned bar, unsigned parity) {
    asm volatile(
        "{\n\t.reg .pred P;\n"
        "W_%=:\n\t"
        "mbarrier.try_wait.parity.acquire.cluster.shared::cta.b64 P, [%0], %1;\n\t"
        "@P bra.uni D_%=;\n\t"
        "bra.uni W_%=;\n\t"
        "D_%=:\n\t}"
        :: "r"(bar), "r"(parity) : "memory");
}
__device__ __forceinline__ void mbar_arrive_rel_cluster(unsigned rem_bar) {
    asm volatile("mbarrier.arrive.release.cluster.shared::cluster.b64 _, [%0];"
                 :: "r"(rem_bar) : "memory");
}
__device__ __forceinline__ void st_cluster_u32(unsigned addr, unsigned v) {
    asm volatile("st.shared::cluster.b32 [%0], %1;" :: "r"(addr), "r"(v) : "memory");
}

// =====================================================================
// Feature kernel: f2 = relu(relu(X@W1.T+b1)@W2.T+b2) -> g_f2h (fp16)
// grid (1024, 2): blockIdx.y = net. 2 CTA/SM.
// =====================================================================
#define XS_STR 72
#define MH_STR 136
#define FG_SMEM (2048 + (128*XS_STR + 128*XS_STR + 128*MH_STR + 128*MH_STR) * 2)

__global__ void __launch_bounds__(256, 2) fg_kernel(
    const float* __restrict__ x,
    const float* __restrict__ a_w1, const float* __restrict__ a_b1,
    const float* __restrict__ a_w2, const float* __restrict__ a_b2,
    const float* __restrict__ c_w1, const float* __restrict__ c_b1,
    const float* __restrict__ c_w2, const float* __restrict__ c_b2)
{
    extern __shared__ __align__(16) char smraw[];
    float* bs1 = (float*)smraw;            // 128
    float* bs2 = bs1 + 128;                // 128
    __half* Xs  = (__half*)(smraw + 2048);
    __half* W1s = Xs  + 128 * XS_STR;
    __half* W2s = W1s + 128 * XS_STR;
    __half* C1s = W2s + 128 * MH_STR;

    int tid = threadIdx.x;
    int net = blockIdx.y;
    size_t rowbase = (size_t)blockIdx.x * 128;

    const float* w1 = net ? c_w1 : a_w1;
    const float* b1 = net ? c_b1 : a_b1;
    const float* w2 = net ? c_w2 : a_w2;
    const float* b2 = net ? c_b2 : a_b2;

    {   // X [128][64]
        const float4* xg = (const float4*)(x + rowbase * SS);
        for (int i = tid; i < 128 * 16; i += 256) {
            int r = i >> 4, c4 = i & 15;
            float4 v = xg[(size_t)r * 16 + c4];
            *(__half2*)&Xs[r * XS_STR + c4 * 4]     = __floats2half2_rn(v.x, v.y);
            *(__half2*)&Xs[r * XS_STR + c4 * 4 + 2] = __floats2half2_rn(v.z, v.w);
        }
    }
    {   // W1 [128][64]
        const float4* wg = (const float4*)w1;
        for (int i = tid; i < 128 * 16; i += 256) {
            int r = i >> 4, c4 = i & 15;
            float4 v = wg[(size_t)r * 16 + c4];
            *(__half2*)&W1s[r * XS_STR + c4 * 4]     = __floats2half2_rn(v.x, v.y);
            *(__half2*)&W1s[r * XS_STR + c4 * 4 + 2] = __floats2half2_rn(v.z, v.w);
        }
    }
    {   // W2 [128][128]
        const float4* wg = (const float4*)w2;
        for (int i = tid; i < 128 * 32; i += 256) {
            int r = i >> 5, c4 = i & 31;
            float4 v = wg[(size_t)r * 32 + c4];
            *(__half2*)&W2s[r * MH_STR + c4 * 4]     = __floats2half2_rn(v.x, v.y);
            *(__half2*)&W2s[r * MH_STR + c4 * 4 + 2] = __floats2half2_rn(v.z, v.w);
        }
    }
    if (tid < 128) { bs1[tid] = __ldg(b1 + tid); bs2[tid] = __ldg(b2 + tid); }
    __syncthreads();

    int wid = tid >> 5, lane = tid & 31;
    int warp_m = wid & 3, warp_n = wid >> 2;
    int m_base = warp_m * 32, n_base = warp_n * 64;

    float acc[2][8][4];

    // stage A: K=64
    #pragma unroll
    for (int mt = 0; mt < 2; mt++)
        #pragma unroll
        for (int nt = 0; nt < 8; nt++)
            #pragma unroll
            for (int q = 0; q < 4; q++) acc[mt][nt][q] = 0.f;

    #pragma unroll
    for (int kt = 0; kt < 4; kt++) {
        int k0 = kt * 16;
        unsigned a[2][4], b[8][2];
        #pragma unroll
        for (int mt = 0; mt < 2; mt++) {
            int r = m_base + mt * 16 + (lane & 15);
            int c = k0 + ((lane >> 4) << 3);
            ldsm4(a[mt], Xs + r * XS_STR + c);
        }
        #pragma unroll
        for (int np = 0; np < 4; np++) {
            int n0 = n_base + np * 16;
            int rr = n0 + ((lane >> 4) << 3) + (lane & 7);
            int cc = k0 + (((lane >> 3) & 1) << 3);
            unsigned t4[4];
            ldsm4(t4, W1s + rr * XS_STR + cc);
            b[np * 2][0] = t4[0]; b[np * 2][1] = t4[1];
            b[np * 2 + 1][0] = t4[2]; b[np * 2 + 1][1] = t4[3];
        }
        #pragma unroll
        for (int mt = 0; mt < 2; mt++)
            #pragma unroll
            for (int nt = 0; nt < 8; nt++)
                mma16816(acc[mt][nt], a[mt], b[nt]);
    }
    #pragma unroll
    for (int mt = 0; mt < 2; mt++) {
        #pragma unroll
        for (int nt = 0; nt < 8; nt++) {
            int r = m_base + mt * 16 + (lane >> 2);
            int c = n_base + nt * 8 + 2 * (lane & 3);
            float v0 = fmaxf(acc[mt][nt][0] + bs1[c], 0.f);
            float v1 = fmaxf(acc[mt][nt][1] + bs1[c + 1], 0.f);
            float v2 = fmaxf(acc[mt][nt][2] + bs1[c], 0.f);
            float v3 = fmaxf(acc[mt][nt][3] + bs1[c + 1], 0.f);
            *(__half2*)&C1s[r * MH_STR + c]       = __floats2half2_rn(v0, v1);
            *(__half2*)&C1s[(r + 8) * MH_STR + c] = __floats2half2_rn(v2, v3);
        }
    }
    __syncthreads();

    // stage B: K=128
    #pragma unroll
    for (int mt = 0; mt < 2; mt++)
        #pragma unroll
        for (int nt = 0; nt < 8; nt++)
            #pragma unroll
            for (int q = 0; q < 4; q++) acc[mt][nt][q] = 0.f;

    #pragma unroll
    for (int kt = 0; kt < 8; kt++) {
        int k0 = kt * 16;
        unsigned a[2][4], b[8][2];
        #pragma unroll
        for (int mt = 0; mt < 2; mt++) {
            int r = m_base + mt * 16 + (lane & 15);
            int c = k0 + ((lane >> 4) << 3);
            ldsm4(a[mt], C1s + r * MH_STR + c);
        }
        #pragma unroll
        for (int np = 0; np < 4; np++) {
            int n0 = n_base + np * 16;
            int rr = n0 + ((lane >> 4) << 3) + (lane & 7);
            int cc = k0 + (((lane >> 3) & 1) << 3);
            unsigned t4[4];
            ldsm4(t4, W2s + rr * MH_STR + cc);
            b[np * 2][0] = t4[0]; b[np * 2][1] = t4[1];
            b[np * 2 + 1][0] = t4[2]; b[np * 2 + 1][1] = t4[3];
        }
        #pragma unroll
        for (int mt = 0; mt < 2; mt++)
            #pragma unroll
            for (int nt = 0; nt < 8; nt++)
                mma16816(acc[mt][nt], a[mt], b[nt]);
    }
    {
        __half* outp = g_f2h + (size_t)net * NROW * HH;
        #pragma unroll
        for (int mt = 0; mt < 2; mt++) {
            #pragma unroll
            for (int nt = 0; nt < 8; nt++) {
                int r = m_base + mt * 16 + (lane >> 2);
                int c = n_base + nt * 8 + 2 * (lane & 3);
                float v0 = fmaxf(acc[mt][nt][0] + bs2[c], 0.f);
                float v1 = fmaxf(acc[mt][nt][1] + bs2[c + 1], 0.f);
                float v2 = fmaxf(acc[mt][nt][2] + bs2[c], 0.f);
                float v3 = fmaxf(acc[mt][nt][3] + bs2[c + 1], 0.f);
                *(__half2*)(outp + (rowbase + r) * (size_t)HH + c) = __floats2half2_rn(v0, v1);
                *(__half2*)(outp + (rowbase + r + 8) * (size_t)HH + c) = __floats2half2_rn(v2, v3);
            }
        }
    }
}

// =====================================================================
// LSTM with fused input projection, cluster-pair j-split.
// f2 staged through a TRIPLE-buffered smem ring; cp.async visibility is
// enforced by CP_WAIT1 before the end-of-step __syncthreads (f2(t+2),
// issued at step t-1, is guaranteed landed before step t+1 reads it).
// Per step: issue f2(t+3) -> local-half h-mma -> x-mma(t+1) [overlaps
// DSMEM push] -> peer wait -> remote-half h-mma -> register epilogue ->
// CP_WAIT1 -> __syncthreads.
// smem (bytes):
//   Ws   [256][136] half (whh, gate-interleaved)   0      .. 69632
//   Wsx  [256][136] half (wih, gate-interleaved)   69632  .. 139264
//   hbuf [2][16][136] half                         139264 .. 147968
//   f2s  [3][16][136] half (rows 8-15 zero)        147968 .. 161024
//   maskb[512] uint                                161024 .. 163072
//   mbars[2] u64                                   163072 .. 163088
// =====================================================================
#define LW_WS  0
#define LW_WX  69632
#define LW_HB  139264
#define LW_F2  147968
#define LW_MB  161024
#define LW_BAR 163072
#define LSTM_SMEM 163104
#define F2BUF 2176   // halves per buffer (16*136)

__global__ void __launch_bounds__(256) __cluster_dims__(2, 1, 1)
lstm_cluster_kernel(const int* __restrict__ dones,
                    const float* __restrict__ a_whh, const float* __restrict__ c_whh,
                    const float* __restrict__ a_wih, const float* __restrict__ c_wih,
                    const float* __restrict__ a_bih, const float* __restrict__ a_bhh,
                    const float* __restrict__ c_bih, const float* __restrict__ c_bhh)
{
    extern __shared__ __align__(16) char sm[];
    __half*   Ws    = (__half*)(sm + LW_WS);
    __half*   Wsx   = (__half*)(sm + LW_WX);
    __half*   hbuf  = (__half*)(sm + LW_HB);
    __half*   f2s   = (__half*)(sm + LW_F2);
    unsigned* maskb = (unsigned*)(sm + LW_MB);

    int tid = threadIdx.x;
    int bx  = blockIdx.x;
    int net = bx >> 6;
    int rowgroup = (bx >> 1) & 31;
    int rb = rowgroup << 3;                       // first of 8 batch rows
    unsigned rank;
    asm("mov.u32 %0, %%cluster_ctarank;" : "=r"(rank));
    unsigned peer = rank ^ 1u;
    int jbase = (int)rank * 64;
    const float* whh = net ? c_whh : a_whh;
    const float* wih = net ? c_wih : a_wih;
    const float* bih = net ? c_bih : a_bih;
    const float* bhh = net ? c_bhh : a_bhh;

    // ---- gate-interleaved weight loads: n -> g=(n>>3)&3, jl=8*(n>>5)+(n&7) ----
    for (int i = tid; i < 256 * 32; i += 256) {
        int n = i >> 5, c4 = i & 31;
        int g  = (n >> 3) & 3;
        int jl = ((n >> 5) << 3) + (n & 7);
        int orig = g * 128 + jbase + jl;
        float4 vh = ((const float4*)whh)[orig * 32 + c4];
        *(__half2*)&Ws[n * 136 + c4 * 4]      = __floats2half2_rn(vh.x, vh.y);
        *(__half2*)&Ws[n * 136 + c4 * 4 + 2]  = __floats2half2_rn(vh.z, vh.w);
        float4 vx = ((const float4*)wih)[orig * 32 + c4];
        *(__half2*)&Wsx[n * 136 + c4 * 4]     = __floats2half2_rn(vx.x, vx.y);
        *(__half2*)&Wsx[n * 136 + c4 * 4 + 2] = __floats2half2_rn(vx.z, vx.w);
    }
    for (int i = tid; i < 2 * 16 * 136; i += 256) hbuf[i] = __float2half(0.f);
    for (int i = tid; i < 3 * 16 * 136; i += 256) f2s[i] = __float2half(0.f);
    for (int s = tid; s < 512; s += 256) {
        unsigned b = 0;
        #pragma unroll
        for (int r = 0; r < 8; r++) b |= ((unsigned)dones[s * 256 + rb + r] & 1u) << r;
        maskb[s] = b;
    }
    unsigned barL0 = smem_u32(sm + LW_BAR);
    unsigned barL1 = barL0 + 8;
    if (tid == 0) {
        asm volatile("mbarrier.init.shared.b64 [%0], %1;" :: "r"(barL0), "r"(256u));
        asm volatile("mbarrier.init.shared.b64 [%0], %1;" :: "r"(barL1), "r"(256u));
    }
    __syncthreads();   // zero-init + barriers visible before any async writes

    const __half* f2g = g_f2h + (size_t)net * NROW * HH;

    // preload f2(0), f2(1), f2(2) -> bufs 0,1,2 (three separate groups)
    #pragma unroll
    for (int s = 0; s < 3; s++) {
        if (tid < 128) {
            int r = tid >> 4, c = tid & 15;
            cpa16(f2s + s * F2BUF + r * 136 + c * 8,
                  f2g + (size_t)(s * 256 + rb + r) * HH + c * 8);
        }
        CP_COMMIT;
    }

    asm volatile("barrier.cluster.arrive.aligned;" ::: "memory");
    asm volatile("barrier.cluster.wait.aligned;" ::: "memory");

    unsigned remBar[2];
    remBar[0] = mapa_u32(barL0, peer);
    remBar[1] = mapa_u32(barL1, peer);

    int lane = tid & 31, wid = tid >> 5;
    int n0w = wid * 32;

    // hoist whh B fragments: 8 kt x 4 n-tiles x 2 regs
    unsigned bfr[8][4][2];
    #pragma unroll
    for (int kt = 0; kt < 8; kt++) {
        int k0 = kt * 16;
        #pragma unroll
        for (int np = 0; np < 2; np++) {
            int rr = n0w + np * 16 + ((lane >> 4) << 3) + (lane & 7);
            int cc = k0 + (((lane >> 3) & 1) << 3);
            unsigned t4[4];
            ldsm4(t4, Ws + rr * 136 + cc);
            bfr[kt][np * 2][0] = t4[0]; bfr[kt][np * 2][1] = t4[1];
            bfr[kt][np * 2 + 1][0] = t4[2]; bfr[kt][np * 2 + 1][1] = t4[3];
        }
    }

    int row = lane >> 2;
    int jlA = 8 * wid + 2 * (lane & 3);
    unsigned remHb[2];
    {
        unsigned base = smem_u32(hbuf);
        #pragma unroll
        for (int buf = 0; buf < 2; buf++) {
            unsigned loc = base + (unsigned)(((buf * 16 + row) * 136 + jbase + jlA) * 2);
            remHb[buf] = mapa_u32(loc, peer);
        }
    }

    // bias regs: gate nt, cols jbase+jlA, jbase+jlA+1
    float brg[4][2];
    #pragma unroll
    for (int nt = 0; nt < 4; nt++) {
        int jj = jbase + jlA;
        brg[nt][0] = __ldg(bih + nt * 128 + jj)     + __ldg(bhh + nt * 128 + jj);
        brg[nt][1] = __ldg(bih + nt * 128 + jj + 1) + __ldg(bhh + nt * 128 + jj + 1);
    }

    // pre-loop: all preloads landed + visible to all threads
    CP_WAIT0;
    __syncthreads();

    // xaccC = bias + f2(0) @ wih^T (buf 0)
    float xaccC[4][4];
    #pragma unroll
    for (int nt = 0; nt < 4; nt++) {
        xaccC[nt][0] = brg[nt][0]; xaccC[nt][1] = brg[nt][1];
        xaccC[nt][2] = brg[nt][0]; xaccC[nt][3] = brg[nt][1];
    }
    #pragma unroll
    for (int kt = 0; kt < 8; kt++) {
        unsigned Ax[4];
        ldsm4(Ax, f2s + (lane & 15) * 136 + kt * 16 + ((lane >> 4) << 3));
        int k0 = kt * 16;
        unsigned bx[4][2];
        #pragma unroll
        for (int np = 0; np < 2; np++) {
            int rr = n0w + np * 16 + ((lane >> 4) << 3) + (lane & 7);
            int cc = k0 + (((lane >> 3) & 1) << 3);
            unsigned t4[4];
            ldsm4(t4, Wsx + rr * 136 + cc);
            bx[np * 2][0] = t4[0]; bx[np * 2][1] = t4[1];
            bx[np * 2 + 1][0] = t4[2]; bx[np * 2 + 1][1] = t4[3];
        }
        #pragma unroll
        for (int nt = 0; nt < 4; nt++)
            mma16816(xaccC[nt], Ax, bx[nt]);
    }
    __syncthreads();   // buf0 reads complete before step 0 overwrites it

    float cstA = 0.f, cstB = 0.f;
    __half* hog = g_hh + (size_t)net * NROW * HH;
    int ph0 = 0, ph1 = 0;
    int ktL0 = (int)rank * 4;        // our-half k tiles
    int ktR0 = 4 - (int)rank * 4;    // peer-half k tiles
    int bufW = 0;                     // (t+3)%3 target = t%3
    int bufR = 1;                     // (t+1)%3

    for (int t = 0; t < TT; t++) {
        bool haveNext = (t < TT - 1);
        // 1. issue f2(t+3) into buf t%3 (holds f2(t), dead after step t-1)
        if (t + 3 < TT && tid < 128) {
            int r = tid >> 4, c = tid & 15;
            cpa16(f2s + bufW * F2BUF + r * 136 + c * 8,
                  f2g + (size_t)((t + 3) * 256 + rb + r) * HH + c * 8);
        }
        CP_COMMIT;

        // 2. local-half h-mma (no peer dependency)
        const __half* hb = hbuf + (t & 1) * (16 * 136);
        float haccL[4][4];
        #pragma unroll
        for (int nt = 0; nt < 4; nt++)
            #pragma unroll
            for (int q = 0; q < 4; q++) haccL[nt][q] = 0.f;
        #pragma unroll
        for (int kq = 0; kq < 4; kq++) {
            int kt = ktL0 + kq;
            unsigned A[4];
            ldsm4(A, hb + (lane & 15) * 136 + kt * 16 + ((lane >> 4) << 3));
            #pragma unroll
            for (int nt = 0; nt < 4; nt++)
                mma16816(haccL[nt], A, bfr[kt][nt]);
        }

        // 3. x-mma for t+1 (overlaps peer DSMEM push); f2(t+1) landed:
        //    issued at step t-2, CP_WAIT1'd at end of step t-1, barrier'd.
        float xaccN[4][4];
        if (haveNext) {
            const __half* fb = f2s + bufR * F2BUF;
            #pragma unroll
            for (int nt = 0; nt < 4; nt++) {
                xaccN[nt][0] = brg[nt][0]; xaccN[nt][1] = brg[nt][1];
                xaccN[nt][2] = brg[nt][0]; xaccN[nt][3] = brg[nt][1];
            }
            #pragma unroll
            for (int kt = 0; kt < 8; kt++) {
                unsigned Ax[4];
                ldsm4(Ax, fb + (lane & 15) * 136 + kt * 16 + ((lane >> 4) << 3));
                int k0 = kt * 16;
                unsigned bx[4][2];
                #pragma unroll
                for (int np = 0; np < 2; np++) {
                    int rr = n0w + np * 16 + ((lane >> 4) << 3) + (lane & 7);
                    int cc = k0 + (((lane >> 3) & 1) << 3);
                    unsigned t4[4];
                    ldsm4(t4, Wsx + rr * 136 + cc);
                    bx[np * 2][0] = t4[0]; bx[np * 2][1] = t4[1];
                    bx[np * 2 + 1][0] = t4[2]; bx[np * 2 + 1][1] = t4[3];
                }
                #pragma unroll
                for (int nt = 0; nt < 4; nt++)
                    mma16816(xaccN[nt], Ax, bx[nt]);
            }
        }

        // 4. peer wait (push likely landed during x-mma)
        if (t > 0) {
            if ((t - 1) & 1) { mbar_wait_acq_cluster(barL1, (unsigned)ph1); ph1 ^= 1; }
            else             { mbar_wait_acq_cluster(barL0, (unsigned)ph0); ph0 ^= 1; }
        }

        // 5. remote-half h-mma
        float haccR[4][4];
        #pragma unroll
        for (int nt = 0; nt < 4; nt++)
            #pragma unroll
            for (int q = 0; q < 4; q++) haccR[nt][q] = 0.f;
        #pragma unroll
        for (int kq = 0; kq < 4; kq++) {
            int kt = ktR0 + kq;
            unsigned A[4];
            ldsm4(A, hb + (lane & 15) * 136 + kt * 16 + ((lane >> 4) << 3));
            #pragma unroll
            for (int nt = 0; nt < 4; nt++)
                mma16816(haccR[nt], A, bfr[kt][nt]);
        }

        // 6. register epilogue
        {
            float iA = sig_t(haccL[0][0] + haccR[0][0] + xaccC[0][0]);
            float iB = sig_t(haccL[0][1] + haccR[0][1] + xaccC[0][1]);
            float fA = sig_t(haccL[1][0] + haccR[1][0] + xaccC[1][0]);
            float fB = sig_t(haccL[1][1] + haccR[1][1] + xaccC[1][1]);
            float gA = tanh_t(haccL[2][0] + haccR[2][0] + xaccC[2][0]);
            float gB = tanh_t(haccL[2][1] + haccR[2][1] + xaccC[2][1]);
            float oA = sig_t(haccL[3][0] + haccR[3][0] + xaccC[3][0]);
            float oB = sig_t(haccL[3][1] + haccR[3][1] + xaccC[3][1]);

            float c2A = fA * cstA + iA * gA;
            float c2B = fB * cstB + iB * gB;
            float h2A = oA * tanh_t(c2A);
            float h2B = oB * tanh_t(c2B);

            float m = ((maskb[t] >> row) & 1u) ? 0.f : 1.f;
            cstA = c2A * m;
            cstB = c2B * m;

            if (haveNext) {
                int nb = (t + 1) & 1;
                __half2 hm = __floats2half2_rn(h2A * m, h2B * m);
                // critical path first: remote push + release-arrive
                st_cluster_u32(remHb[nb], *(unsigned*)&hm);
                mbar_arrive_rel_cluster(remBar[t & 1]);
                // local (off critical path)
                *(__half2*)&hbuf[(nb * 16 + row) * 136 + jbase + jlA] = hm;
                // rotate xacc (rows 8-15 of the m16 tile are padding)
                #pragma unroll
                for (int nt = 0; nt < 4; nt++) {
                    xaccC[nt][0] = xaccN[nt][0];
                    xaccC[nt][1] = xaccN[nt][1];
                }
            }
            *(__half2*)(hog + (size_t)(t * 256 + rb + row) * HH + jbase + jlA)
                = __floats2half2_rn(h2A, h2B);
        }

        // 7. cp.async ordering: guarantee f2(t+2) (issued step t-1) landed
        //    before the barrier, so step t+1's x-mma reads are safe.
        CP_WAIT1;
        __syncthreads();

        if (++bufW == 3) bufW = 0;
        if (++bufR == 3) bufR = 0;
    }

    asm volatile("barrier.cluster.arrive.aligned;" ::: "memory");
    asm volatile("barrier.cluster.wait.aligned;" ::: "memory");
}

// =====================================================================
// Heads on HMMA (unchanged from R8)
// =====================================================================
#define HD_HA 0
#define HD_HC 34816
#define HD_W  69632
#define HD_B  78336
#define HD_SMEM 78464

__global__ void __launch_bounds__(256) heads_mma_kernel(
    const float* __restrict__ mw, const float* __restrict__ mb,
    const float* __restrict__ lw, const float* __restrict__ lb,
    const float* __restrict__ vw, const float* __restrict__ vb,
    float* __restrict__ out)
{
    extern __shared__ __align__(16) char sm[];
    __half* Ha = (__half*)(sm + HD_HA);   // [128][136]
    __half* Hc = (__half*)(sm + HD_HC);   // [128][136]
    __half* Wh = (__half*)(sm + HD_W);    // [32][136]
    float*  bsm = (float*)(sm + HD_B);

    int tid = threadIdx.x;
    size_t rowbase = (size_t)blockIdx.x * 128;

    const __half* ha = g_hh + rowbase * HH;
    const __half* hc = g_hh + (size_t)NROW * HH + rowbase * HH;
    for (int i = tid; i < 2048; i += 256) {
        int r = i >> 4, c = i & 15;
        cpa16(Ha + r * 136 + c * 8, ha + (size_t)r * HH + c * 8);
        cpa16(Hc + r * 136 + c * 8, hc + (size_t)r * HH + c * 8);
    }
    CP_COMMIT;
    for (int i = tid; i < 4096; i += 256) {
        int r = i >> 7, c = i & 127;
        float v = 0.f;
        if (r < 8) v = mw[r * 128 + c];
        else if (r < 16) v = lw[(r - 8) * 128 + c];
        else if (r == 16) v = vw[c];
        Wh[r * 136 + c] = __float2half(v);
    }
    if (tid < 8) { bsm[tid] = mb[tid]; bsm[8 + tid] = lb[tid]; }
    if (tid == 16) bsm[16] = vb[0];
    CP_WAIT0;
    __syncthreads();

    int wid = tid >> 5, lane = tid & 31;
    int r0 = wid * 16;

    unsigned bf[8][3][2];
    #pragma unroll
    for (int kt = 0; kt < 8; kt++) {
        int k0 = kt * 16;
        {
            int rr = ((lane >> 4) << 3) + (lane & 7);
            int cc = k0 + (((lane >> 3) & 1) << 3);
            unsigned t4[4];
            ldsm4(t4, Wh + rr * 136 + cc);
            bf[kt][0][0] = t4[0]; bf[kt][0][1] = t4[1];
            bf[kt][1][0] = t4[2]; bf[kt][1][1] = t4[3];
        }
        {
            int rr = 16 + ((lane >> 4) << 3) + (lane & 7);
            int cc = k0 + (((lane >> 3) & 1) << 3);
            unsigned t4[4];
            ldsm4(t4, Wh + rr * 136 + cc);
            bf[kt][2][0] = t4[0]; bf[kt][2][1] = t4[1];
        }
    }

    float accM[4], accL[4], accV[4];
    #pragma unroll
    for (int q = 0; q < 4; q++) { accM[q] = 0.f; accL[q] = 0.f; accV[q] = 0.f; }

    #pragma unroll
    for (int kt = 0; kt < 8; kt++) {
        int k0 = kt * 16;
        unsigned a[4], cfr[4];
        ldsm4(a,   Ha + (r0 + (lane & 15)) * 136 + k0 + ((lane >> 4) << 3));
        ldsm4(cfr, Hc + (r0 + (lane & 15)) * 136 + k0 + ((lane >> 4) << 3));
        mma16816(accM, a, bf[kt][0]);
        mma16816(accL, a, bf[kt][1]);
        mma16816(accV, cfr, bf[kt][2]);
    }

    int row = lane >> 2, c0 = 2 * (lane & 3);
    size_t gr0 = rowbase + r0 + row;
    size_t gr1 = gr0 + 8;
    *(float2*)(out + gr0 * 8 + c0) = make_float2(accM[0] + bsm[c0], accM[1] + bsm[c0 + 1]);
    *(float2*)(out + gr1 * 8 + c0) = make_float2(accM[2] + bsm[c0], accM[3] + bsm[c0 + 1]);
    float* outs = out + (size_t)NROW * 8;
    *(float2*)(outs + gr0 * 8 + c0) =
        make_float2(__expf(accL[0] + bsm[8 + c0]), __expf(accL[1] + bsm[8 + c0 + 1]));
    *(float2*)(outs + gr1 * 8 + c0) =
        make_float2(__expf(accL[2] + bsm[8 + c0]), __expf(accL[3] + bsm[8 + c0 + 1]));
    if ((lane & 3) == 0) {
        float* outv = out + (size_t)NROW * 16;
        outv[gr0] = accV[0] + bsm[16];
        outv[gr1] = accV[2] + bsm[16];
    }
}

// ---------------- launch ----------------
extern "C" void kernel_launch(void* const* d_in, const int* in_sizes, int n_in,
                              void* d_out, int out_size)
{
    const float* state  = (const float*)d_in[0];
    const int*   dones  = (const int*)d_in[1];
    const float* a_w1   = (const float*)d_in[2];
    const float* a_b1   = (const float*)d_in[3];
    const float* a_w2   = (const float*)d_in[4];
    const float* a_b2   = (const float*)d_in[5];
    const float* c_w1   = (const float*)d_in[6];
    const float* c_b1   = (const float*)d_in[7];
    const float* c_w2   = (const float*)d_in[8];
    const float* c_b2   = (const float*)d_in[9];
    const float* a_wih  = (const float*)d_in[10];
    const float* a_whh  = (const float*)d_in[11];
    const float* a_bih  = (const float*)d_in[12];
    const float* a_bhh  = (const float*)d_in[13];
    const float* c_wih  = (const float*)d_in[14];
    const float* c_whh  = (const float*)d_in[15];
    const float* c_bih  = (const float*)d_in[16];
    const float* c_bhh  = (const float*)d_in[17];
    const float* mean_w = (const float*)d_in[18];
    const float* mean_b = (const float*)d_in[19];
    const float* lstd_w = (const float*)d_in[20];
    const float* lstd_b = (const float*)d_in[21];
    const float* val_w  = (const float*)d_in[22];
    const float* val_b  = (const float*)d_in[23];

    cudaFuncSetAttribute(fg_kernel, cudaFuncAttributeMaxDynamicSharedMemorySize, FG_SMEM);
    cudaFuncSetAttribute(lstm_cluster_kernel, cudaFuncAttributeMaxDynamicSharedMemorySize, LSTM_SMEM);
    cudaFuncSetAttribute(heads_mma_kernel, cudaFuncAttributeMaxDynamicSharedMemorySize, HD_SMEM);

    dim3 fgg(1024, 2);
    fg_kernel<<<fgg, 256, FG_SMEM>>>(state,
                                     a_w1, a_b1, a_w2, a_b2,
                                     c_w1, c_b1, c_w2, c_b2);

    lstm_cluster_kernel<<<128, 256, LSTM_SMEM>>>(dones, a_whh, c_whh,
                                                 a_wih, c_wih,
                                                 a_bih, a_bhh, c_bih, c_bhh);

    heads_mma_kernel<<<1024, 256, HD_SMEM>>>(mean_w, mean_b, lstd_w, lstd_b,
                                             val_w, val_b, (float*)d_out);
}

// round 12
// speedup vs baseline: 1.3477x; 1.3477x over previous
#include <cuda_runtime.h>
#include <cuda_fp16.h>

// Problem dims
#define TT 512
#define BB 256
#define SS 64
#define HH 128
#define NROW (TT*BB)          // 131072

// ---------------- scratch (device globals; no allocation allowed) ----------------
__device__ __half g_gxh[(size_t)2 * NROW * 512];     // gx fp16 (268MB)
__device__ __half g_hh [(size_t)2 * NROW * HH];      // LSTM hidden outputs fp16 (67MB)
__device__ __half g_wih16[2 * 512 * 128];            // wih packed fp16

// ---------------- helpers ----------------
__device__ __forceinline__ float tanh_t(float x) {
    float y; asm("tanh.approx.f32 %0, %1;" : "=f"(y) : "f"(x)); return y;
}
__device__ __forceinline__ float sig_t(float x) {
    return fmaf(tanh_t(x * 0.5f), 0.5f, 0.5f);
}
__device__ __forceinline__ void mma16816(float* c, const unsigned* a, const unsigned* b) {
    asm volatile(
        "mma.sync.aligned.m16n8k16.row.col.f32.f16.f16.f32 "
        "{%0,%1,%2,%3}, {%4,%5,%6,%7}, {%8,%9}, {%0,%1,%2,%3};\n"
        : "+f"(c[0]), "+f"(c[1]), "+f"(c[2]), "+f"(c[3])
        : "r"(a[0]), "r"(a[1]), "r"(a[2]), "r"(a[3]), "r"(b[0]), "r"(b[1]));
}
__device__ __forceinline__ void ldsm4(unsigned* d, const __half* p) {
    unsigned addr = (unsigned)__cvta_generic_to_shared((void*)p);
    asm volatile("ldmatrix.sync.aligned.m8n8.x4.shared.b16 {%0,%1,%2,%3}, [%4];\n"
                 : "=r"(d[0]), "=r"(d[1]), "=r"(d[2]), "=r"(d[3]) : "r"(addr));
}
__device__ __forceinline__ unsigned smem_u32(const void* p) {
    return (unsigned)__cvta_generic_to_shared((void*)p);
}
__device__ __forceinline__ void cpa16(void* smem_dst, const void* gsrc) {
    unsigned s = smem_u32(smem_dst);
    asm volatile("cp.async.cg.shared.global [%0], [%1], 16;" :: "r"(s), "l"(gsrc));
}
#define CP_COMMIT asm volatile("cp.async.commit_group;" ::: "memory")
#define CP_WAIT0  asm volatile("cp.async.wait_group 0;" ::: "memory")

__device__ __forceinline__ unsigned mapa_u32(unsigned addr, unsigned rank) {
    unsigned r;
    asm("mapa.shared::cluster.u32 %0, %1, %2;" : "=r"(r) : "r"(addr), "r"(rank));
    return r;
}
__device__ __forceinline__ void mbar_wait_acq_cluster(unsigned bar, unsigned parity) {
    asm volatile(
        "{\n\t.reg .pred P;\n"
        "W_%=:\n\t"
        "mbarrier.try_wait.parity.acquire.cluster.shared::cta.b64 P, [%0], %1;\n\t"
        "@P bra.uni D_%=;\n\t"
        "bra.uni W_%=;\n\t"
        "D_%=:\n\t}"
        :: "r"(bar), "r"(parity) : "memory");
}
__device__ __forceinline__ void mbar_arrive_rel_cluster(unsigned rem_bar) {
    asm volatile("mbarrier.arrive.release.cluster.shared::cluster.b64 _, [%0];"
                 :: "r"(rem_bar) : "memory");
}
__device__ __forceinline__ void st_cluster_u32(unsigned addr, unsigned v) {
    asm volatile("st.shared::cluster.b32 [%0], %1;" :: "r"(addr), "r"(v) : "memory");
}

// ---------------- pack wih -> fp16 ----------------
__global__ void pack16_kernel(const float* __restrict__ a_wih, const float* __restrict__ c_wih) {
    int idx = blockIdx.x * blockDim.x + threadIdx.x;
    if (idx >= 2 * 65536) return;
    int net = idx >> 16, r = idx & 65535;
    g_wih16[idx] = __float2half((net ? c_wih : a_wih)[r]);
}

// =====================================================================
// Fused feature kernel (exact R8): f2 = relu(relu(X@W1.T+b1)@W2.T+b2),
// then gx = f2 @ wih.T + (bih+bhh). launch_bounds(256,2) -> 2 CTA/SM.
// =====================================================================
#define XS_STR 72
#define MH_STR 136
#define FG_BS  0
#define FG_XS  3072
#define FG_W1S 21504
#define FG_W2S 39936
#define FG_C1S 74752
#define FG_SMEM 109568

__global__ void __launch_bounds__(256, 2) fg_kernel(
    const float* __restrict__ x,
    const float* __restrict__ a_w1, const float* __restrict__ a_b1,
    const float* __restrict__ a_w2, const float* __restrict__ a_b2,
    const float* __restrict__ c_w1, const float* __restrict__ c_b1,
    const float* __restrict__ c_w2, const float* __restrict__ c_b2,
    const float* __restrict__ a_bih, const float* __restrict__ a_bhh,
    const float* __restrict__ c_bih, const float* __restrict__ c_bhh)
{
    extern __shared__ __align__(16) char smraw[];
    float*  bs1  = (float*)(smraw + FG_BS);        // 128
    float*  bs2  = bs1 + 128;                      // 128
    float*  bsum = bs2 + 128;                      // 512
    __half* Xs   = (__half*)(smraw + FG_XS);       // stride 72
    __half* W1s  = (__half*)(smraw + FG_W1S);      // stride 72
    __half* W2s  = (__half*)(smraw + FG_W2S);      // stride 136
    __half* C1s  = (__half*)(smraw + FG_C1S);      // stride 136
    __half* F2s  = (__half*)(smraw + FG_XS);       // stride 136 (overlays Xs+W1s)
    __half* Wb[2]; Wb[0] = W2s; Wb[1] = C1s;

    int tid = threadIdx.x;
    int net = blockIdx.y;
    size_t rowbase = (size_t)blockIdx.x * 128;

    const float* w1 = net ? c_w1 : a_w1;
    const float* b1 = net ? c_b1 : a_b1;
    const float* w2 = net ? c_w2 : a_w2;
    const float* b2 = net ? c_b2 : a_b2;
    const float* bih = net ? c_bih : a_bih;
    const float* bhh = net ? c_bhh : a_bhh;

    {   // X [128][64]
        const float4* xg = (const float4*)(x + rowbase * SS);
        for (int i = tid; i < 128 * 16; i += 256) {
            int r = i >> 4, c4 = i & 15;
            float4 v = xg[(size_t)r * 16 + c4];
            *(__half2*)&Xs[r * XS_STR + c4 * 4]     = __floats2half2_rn(v.x, v.y);
            *(__half2*)&Xs[r * XS_STR + c4 * 4 + 2] = __floats2half2_rn(v.z, v.w);
        }
    }
    {   // W1 [128][64]
        const float4* wg = (const float4*)w1;
        for (int i = tid; i < 128 * 16; i += 256) {
            int r = i >> 4, c4 = i & 15;
            float4 v = wg[(size_t)r * 16 + c4];
            *(__half2*)&W1s[r * XS_STR + c4 * 4]     = __floats2half2_rn(v.x, v.y);
            *(__half2*)&W1s[r * XS_STR + c4 * 4 + 2] = __floats2half2_rn(v.z, v.w);
        }
    }
    {   // W2 [128][128]
        const float4* wg = (const float4*)w2;
        for (int i = tid; i < 128 * 32; i += 256) {
            int r = i >> 5, c4 = i & 31;
            float4 v = wg[(size_t)r * 32 + c4];
            *(__half2*)&W2s[r * MH_STR + c4 * 4]     = __floats2half2_rn(v.x, v.y);
            *(__half2*)&W2s[r * MH_STR + c4 * 4 + 2] = __floats2half2_rn(v.z, v.w);
        }
    }
    if (tid < 128) { bs1[tid] = __ldg(b1 + tid); bs2[tid] = __ldg(b2 + tid); }
    for (int i = tid; i < 512; i += 256) bsum[i] = __ldg(bih + i) + __ldg(bhh + i);
    __syncthreads();

    int wid = tid >> 5, lane = tid & 31;
    int warp_m = wid & 3, warp_n = wid >> 2;
    int m_base = warp_m * 32, n_base = warp_n * 64;

    float acc[2][8][4];

    // -------- stage A: C1 = relu(X @ W1.T + b1), K=64 --------
    #pragma unroll
    for (int mt = 0; mt < 2; mt++)
        #pragma unroll
        for (int nt = 0; nt < 8; nt++)
            #pragma unroll
            for (int q = 0; q < 4; q++) acc[mt][nt][q] = 0.f;

    #pragma unroll
    for (int kt = 0; kt < 4; kt++) {
        int k0 = kt * 16;
        unsigned a[2][4], b[8][2];
        #pragma unroll
        for (int mt = 0; mt < 2; mt++) {
            int r = m_base + mt * 16 + (lane & 15);
            int c = k0 + ((lane >> 4) << 3);
            ldsm4(a[mt], Xs + r * XS_STR + c);
        }
        #pragma unroll
        for (int np = 0; np < 4; np++) {
            int n0 = n_base + np * 16;
            int rr = n0 + ((lane >> 4) << 3) + (lane & 7);
            int cc = k0 + (((lane >> 3) & 1) << 3);
            unsigned t4[4];
            ldsm4(t4, W1s + rr * XS_STR + cc);
            b[np * 2][0] = t4[0]; b[np * 2][1] = t4[1];
            b[np * 2 + 1][0] = t4[2]; b[np * 2 + 1][1] = t4[3];
        }
        #pragma unroll
        for (int mt = 0; mt < 2; mt++)
            #pragma unroll
            for (int nt = 0; nt < 8; nt++)
                mma16816(acc[mt][nt], a[mt], b[nt]);
    }
    #pragma unroll
    for (int mt = 0; mt < 2; mt++) {
        #pragma unroll
        for (int nt = 0; nt < 8; nt++) {
            int r = m_base + mt * 16 + (lane >> 2);
            int c = n_base + nt * 8 + 2 * (lane & 3);
            float v0 = fmaxf(acc[mt][nt][0] + bs1[c], 0.f);
            float v1 = fmaxf(acc[mt][nt][1] + bs1[c + 1], 0.f);
            float v2 = fmaxf(acc[mt][nt][2] + bs1[c], 0.f);
            float v3 = fmaxf(acc[mt][nt][3] + bs1[c + 1], 0.f);
            *(__half2*)&C1s[r * MH_STR + c]       = __floats2half2_rn(v0, v1);
            *(__half2*)&C1s[(r + 8) * MH_STR + c] = __floats2half2_rn(v2, v3);
        }
    }
    __syncthreads();

    // -------- stage B: F2 = relu(C1 @ W2.T + b2), K=128 --------
    #pragma unroll
    for (int mt = 0; mt < 2; mt++)
        #pragma unroll
        for (int nt = 0; nt < 8; nt++)
            #pragma unroll
            for (int q = 0; q < 4; q++) acc[mt][nt][q] = 0.f;

    #pragma unroll
    for (int kt = 0; kt < 8; kt++) {
        int k0 = kt * 16;
        unsigned a[2][4], b[8][2];
        #pragma unroll
        for (int mt = 0; mt < 2; mt++) {
            int r = m_base + mt * 16 + (lane & 15);
            int c = k0 + ((lane >> 4) << 3);
            ldsm4(a[mt], C1s + r * MH_STR + c);
        }
        #pragma unroll
        for (int np = 0; np < 4; np++) {
            int n0 = n_base + np * 16;
            int rr = n0 + ((lane >> 4) << 3) + (lane & 7);
            int cc = k0 + (((lane >> 3) & 1) << 3);
            unsigned t4[4];
            ldsm4(t4, W2s + rr * MH_STR + cc);
            b[np * 2][0] = t4[0]; b[np * 2][1] = t4[1];
            b[np * 2 + 1][0] = t4[2]; b[np * 2 + 1][1] = t4[3];
        }
        #pragma unroll
        for (int mt = 0; mt < 2; mt++)
            #pragma unroll
            for (int nt = 0; nt < 8; nt++)
                mma16816(acc[mt][nt], a[mt], b[nt]);
    }
    // epilogue B -> F2s (smem, overlays Xs/W1s — dead after stage A/B barriers)
    #pragma unroll
    for (int mt = 0; mt < 2; mt++) {
        #pragma unroll
        for (int nt = 0; nt < 8; nt++) {
            int r = m_base + mt * 16 + (lane >> 2);
            int c = n_base + nt * 8 + 2 * (lane & 3);
            float v0 = fmaxf(acc[mt][nt][0] + bs2[c], 0.f);
            float v1 = fmaxf(acc[mt][nt][1] + bs2[c + 1], 0.f);
            float v2 = fmaxf(acc[mt][nt][2] + bs2[c], 0.f);
            float v3 = fmaxf(acc[mt][nt][3] + bs2[c + 1], 0.f);
            *(__half2*)&F2s[r * MH_STR + c]       = __floats2half2_rn(v0, v1);
            *(__half2*)&F2s[(r + 8) * MH_STR + c] = __floats2half2_rn(v2, v3);
        }
    }
    __syncthreads();   // F2s complete; W2s/C1s reads complete -> reuse as Wb

    // -------- gx phase: loop 4 weight chunks; A re-ldsm'd from F2s --------
    const __half* wsrc = g_wih16 + (size_t)net * 65536;

    for (int i = tid; i < 2048; i += 256) {
        int r = i >> 4, c = i & 15;
        cpa16(Wb[0] + r * MH_STR + c * 8, wsrc + r * 128 + c * 8);
    }
    CP_COMMIT;
    CP_WAIT0;
    __syncthreads();

    __half* outp = g_gxh + (size_t)net * NROW * 512;

    #pragma unroll
    for (int ch = 0; ch < 4; ch++) {
        if (ch < 3) {
            const __half* src = wsrc + (ch + 1) * 128 * 128;
            __half* dst = Wb[(ch + 1) & 1];
            for (int i = tid; i < 2048; i += 256) {
                int r = i >> 4, c = i & 15;
                cpa16(dst + r * MH_STR + c * 8, src + r * 128 + c * 8);
            }
            CP_COMMIT;
        }
        const __half* Ws = Wb[ch & 1];

        #pragma unroll
        for (int mt = 0; mt < 2; mt++)
            #pragma unroll
            for (int nt = 0; nt < 8; nt++)
                #pragma unroll
                for (int q = 0; q < 4; q++) acc[mt][nt][q] = 0.f;

        #pragma unroll
        for (int kt = 0; kt < 8; kt++) {
            int k0 = kt * 16;
            unsigned a[2][4], b[8][2];
            #pragma unroll
            for (int mt = 0; mt < 2; mt++) {
                int r = m_base + mt * 16 + (lane & 15);
                int c = k0 + ((lane >> 4) << 3);
                ldsm4(a[mt], F2s + r * MH_STR + c);
            }
            #pragma unroll
            for (int np = 0; np < 4; np++) {
                int n0 = n_base + np * 16;
                int rr = n0 + ((lane >> 4) << 3) + (lane & 7);
                int cc = k0 + (((lane >> 3) & 1) << 3);
                unsigned t4[4];
                ldsm4(t4, Ws + rr * MH_STR + cc);
                b[np * 2][0] = t4[0]; b[np * 2][1] = t4[1];
                b[np * 2 + 1][0] = t4[2]; b[np * 2 + 1][1] = t4[3];
            }
            #pragma unroll
            for (int mt = 0; mt < 2; mt++)
                #pragma unroll
                for (int nt = 0; nt < 8; nt++)
                    mma16816(acc[mt][nt], a[mt], b[nt]);
        }
        #pragma unroll
        for (int mt = 0; mt < 2; mt++) {
            #pragma unroll
            for (int nt = 0; nt < 8; nt++) {
                int r = m_base + mt * 16 + (lane >> 2);
                int c = n_base + nt * 8 + 2 * (lane & 3);
                int gc = ch * 128 + c;
                float v0 = acc[mt][nt][0] + bsum[gc];
                float v1 = acc[mt][nt][1] + bsum[gc + 1];
                float v2 = acc[mt][nt][2] + bsum[gc];
                float v3 = acc[mt][nt][3] + bsum[gc + 1];
                *(__half2*)(outp + (rowbase + r) * (size_t)512 + gc) = __floats2half2_rn(v0, v1);
                *(__half2*)(outp + (rowbase + r + 8) * (size_t)512 + gc) = __floats2half2_rn(v2, v3);
            }
        }
        if (ch < 3) {
            CP_WAIT0;
            __syncthreads();
        }
    }
}

// =====================================================================
// LSTM recurrence (R8 base), cluster-pair j-split, gate-interleaved Ws.
// CHANGE vs R8: remote mbarrier arrive count 256 -> 1. Per-thread data
// pushes stay early (latency-optimal); after the end-of-step
// __syncthreads (HB from all pushes), ONE elected thread issues
// fence.acq_rel.cluster + release-arrive on the peer barrier.
// =====================================================================
#define LW_WS  0
#define LW_HB  69632
#define LW_GX  78336
#define LW_MB  86784
#define LW_BAR 88832
#define LSTM_SMEM 88864

__global__ void __launch_bounds__(256) __cluster_dims__(2, 1, 1)
lstm_cluster_kernel(const int* __restrict__ dones,
                    const float* __restrict__ a_whh, const float* __restrict__ c_whh)
{
    extern __shared__ __align__(16) char sm[];
    __half*   Ws    = (__half*)(sm + LW_WS);
    __half*   hbuf  = (__half*)(sm + LW_HB);
    __half*   gxs   = (__half*)(sm + LW_GX);
    unsigned* maskb = (unsigned*)(sm + LW_MB);

    int tid = threadIdx.x;
    int bx  = blockIdx.x;
    int net = bx >> 6;
    int rowgroup = (bx >> 1) & 31;
    int rb = rowgroup << 3;                       // first of 8 batch rows
    unsigned rank;
    asm("mov.u32 %0, %%cluster_ctarank;" : "=r"(rank));
    unsigned peer = rank ^ 1u;
    int jbase = (int)rank * 64;
    const float* whh = net ? c_whh : a_whh;

    // ---- gate-interleaved whh rows: n -> g=(n>>3)&3, jl=8*(n>>5)+(n&7) ----
    for (int i = tid; i < 256 * 32; i += 256) {
        int n = i >> 5, c4 = i & 31;
        int g  = (n >> 3) & 3;
        int jl = ((n >> 5) << 3) + (n & 7);
        int orig = g * 128 + jbase + jl;
        float4 v = ((const float4*)whh)[orig * 32 + c4];
        *(__half2*)&Ws[n * 136 + c4 * 4]     = __floats2half2_rn(v.x, v.y);
        *(__half2*)&Ws[n * 136 + c4 * 4 + 2] = __floats2half2_rn(v.z, v.w);
    }
    for (int i = tid; i < 2 * 16 * 136; i += 256) hbuf[i] = __float2half(0.f);
    for (int s = tid; s < 512; s += 256) {
        unsigned b = 0;
        #pragma unroll
        for (int r = 0; r < 8; r++) b |= ((unsigned)dones[s * 256 + rb + r] & 1u) << r;
        maskb[s] = b;
    }
    const __half* gxg = g_gxh + (size_t)net * NROW * 512;
    {
        int row = tid >> 5, rem = tid & 31, seg = rem >> 3, q = rem & 7;
        uint4 v = *(const uint4*)(gxg + (size_t)(rb + row) * 512 + seg * 128 + jbase + q * 8);
        ((uint4*)gxs)[33 * row + 8 * seg + q] = v;
    }
    unsigned barL0 = smem_u32(sm + LW_BAR);
    unsigned barL1 = barL0 + 8;
    if (tid == 0) {
        asm volatile("mbarrier.init.shared.b64 [%0], %1;" :: "r"(barL0), "r"(1u));
        asm volatile("mbarrier.init.shared.b64 [%0], %1;" :: "r"(barL1), "r"(1u));
    }
    __syncthreads();
    asm volatile("barrier.cluster.arrive.aligned;" ::: "memory");
    asm volatile("barrier.cluster.wait.aligned;" ::: "memory");

    unsigned remBar[2];
    remBar[0] = mapa_u32(barL0, peer);
    remBar[1] = mapa_u32(barL1, peer);

    int lane = tid & 31, wid = tid >> 5;
    int n0w = wid * 32;

    // hoist B fragments: 8 kt x 4 n-tiles x 2 regs
    unsigned bfr[8][4][2];
    #pragma unroll
    for (int kt = 0; kt < 8; kt++) {
        int k0 = kt * 16;
        #pragma unroll
        for (int np = 0; np < 2; np++) {
            int rr = n0w + np * 16 + ((lane >> 4) << 3) + (lane & 7);
            int cc = k0 + (((lane >> 3) & 1) << 3);
            unsigned t4[4];
            ldsm4(t4, Ws + rr * 136 + cc);
            bfr[kt][np * 2][0] = t4[0]; bfr[kt][np * 2][1] = t4[1];
            bfr[kt][np * 2 + 1][0] = t4[2]; bfr[kt][np * 2 + 1][1] = t4[3];
        }
    }

    int row = lane >> 2;
    int jlA = 8 * wid + 2 * (lane & 3);
    unsigned remHb[2];
    {
        unsigned base = smem_u32(hbuf);
        #pragma unroll
        for (int buf = 0; buf < 2; buf++) {
            unsigned loc = base + (unsigned)(((buf * 16 + row) * 136 + jbase + jlA) * 2);
            remHb[buf] = mapa_u32(loc, peer);
        }
    }

    float cstA = 0.f, cstB = 0.f;
    __half* hog = g_hh + (size_t)net * NROW * HH;
    int ph0 = 0, ph1 = 0;

    for (int t = 0; t < TT; t++) {
        bool haveNext = (t < TT - 1);
        uint4 pf;
        if (haveNext) {
            int prow = tid >> 5, rem = tid & 31, seg = rem >> 3, q = rem & 7;
            pf = *(const uint4*)(gxg + (size_t)((t + 1) * 256 + rb + prow) * 512
                                 + seg * 128 + jbase + q * 8);
        }
        if (t > 0) {
            if ((t - 1) & 1) { mbar_wait_acq_cluster(barL1, (unsigned)ph1); ph1 ^= 1; }
            else             { mbar_wait_acq_cluster(barL0, (unsigned)ph0); ph0 ^= 1; }
        }

        const __half* hb = hbuf + (t & 1) * (16 * 136);
        unsigned A[8][4];
        #pragma unroll
        for (int kt = 0; kt < 8; kt++)
            ldsm4(A[kt], hb + (lane & 15) * 136 + kt * 16 + ((lane >> 4) << 3));

        float acc[4][4];
        #pragma unroll
        for (int nt = 0; nt < 4; nt++)
            #pragma unroll
            for (int q = 0; q < 4; q++) acc[nt][q] = 0.f;

        #pragma unroll
        for (int kt = 0; kt < 8; kt++)
            #pragma unroll
            for (int nt = 0; nt < 4; nt++)
                mma16816(acc[nt], A[kt], bfr[kt][nt]);

        // ---- register epilogue; DSMEM data push early, NO per-thread arrive ----
        {
            const __half* gxcur = gxs + (t & 1) * 2112;
            const __half* gp = gxcur + row * 264 + jlA;
            float2 f0 = __half22float2(*(const __half2*)(gp));
            float2 f1 = __half22float2(*(const __half2*)(gp + 64));
            float2 f2v = __half22float2(*(const __half2*)(gp + 128));
            float2 f3 = __half22float2(*(const __half2*)(gp + 192));

            float iA = sig_t(acc[0][0] + f0.x), iB = sig_t(acc[0][1] + f0.y);
            float fA = sig_t(acc[1][0] + f1.x), fB = sig_t(acc[1][1] + f1.y);
            float gA = tanh_t(acc[2][0] + f2v.x), gB = tanh_t(acc[2][1] + f2v.y);
            float oA = sig_t(acc[3][0] + f3.x), oB = sig_t(acc[3][1] + f3.y);

            float c2A = fA * cstA + iA * gA;
            float c2B = fB * cstB + iB * gB;
            float h2A = oA * tanh_t(c2A);
            float h2B = oB * tanh_t(c2B);

            float m = ((maskb[t] >> row) & 1u) ? 0.f : 1.f;
            cstA = c2A * m;
            cstB = c2B * m;

            if (haveNext) {
                int nb = (t + 1) & 1;
                __half2 hm = __floats2half2_rn(h2A * m, h2B * m);
                // remote data push ASAP (in flight during rest of epilogue)
                st_cluster_u32(remHb[nb], *(unsigned*)&hm);
                // local stores
                *(__half2*)&hbuf[(nb * 16 + row) * 136 + jbase + jlA] = hm;
                {
                    int prow = tid >> 5, rem = tid & 31, seg = rem >> 3, q = rem & 7;
                    ((uint4*)(gxs + nb * 2112))[33 * prow + 8 * seg + q] = pf;
                }
            }
            *(__half2*)(hog + (size_t)(t * 256 + rb + row) * HH + jbase + jlA)
                = __floats2half2_rn(h2A, h2B);
        }
        __syncthreads();
        // single release-arrive: HB from all threads' pushes via the barrier,
        // made cluster-visible by the fence, signaled by ONE remote arrive.
        if (haveNext && tid == 0) {
            asm volatile("fence.acq_rel.cluster;" ::: "memory");
            mbar_arrive_rel_cluster(remBar[t & 1]);
        }
    }

    asm volatile("barrier.cluster.arrive.aligned;" ::: "memory");
    asm volatile("barrier.cluster.wait.aligned;" ::: "memory");
}

// =====================================================================
// Heads on HMMA (exact R8)
// =====================================================================
#define HD_HA 0
#define HD_HC 34816
#define HD_W  69632
#define HD_B  78336
#define HD_SMEM 78464

__global__ void __launch_bounds__(256) heads_mma_kernel(
    const float* __restrict__ mw, const float* __restrict__ mb,
    const float* __restrict__ lw, const float* __restrict__ lb,
    const float* __restrict__ vw, const float* __restrict__ vb,
    float* __restrict__ out)
{
    extern __shared__ __align__(16) char sm[];
    __half* Ha = (__half*)(sm + HD_HA);   // [128][136]
    __half* Hc = (__half*)(sm + HD_HC);   // [128][136]
    __half* Wh = (__half*)(sm + HD_W);    // [32][136]
    float*  bsm = (float*)(sm + HD_B);

    int tid = threadIdx.x;
    size_t rowbase = (size_t)blockIdx.x * 128;

    const __half* ha = g_hh + rowbase * HH;
    const __half* hc = g_hh + (size_t)NROW * HH + rowbase * HH;
    for (int i = tid; i < 2048; i += 256) {
        int r = i >> 4, c = i & 15;
        cpa16(Ha + r * 136 + c * 8, ha + (size_t)r * HH + c * 8);
        cpa16(Hc + r * 136 + c * 8, hc + (size_t)r * HH + c * 8);
    }
    CP_COMMIT;
    for (int i = tid; i < 4096; i += 256) {
        int r = i >> 7, c = i & 127;
        float v = 0.f;
        if (r < 8) v = mw[r * 128 + c];
        else if (r < 16) v = lw[(r - 8) * 128 + c];
        else if (r == 16) v = vw[c];
        Wh[r * 136 + c] = __float2half(v);
    }
    if (tid < 8) { bsm[tid] = mb[tid]; bsm[8 + tid] = lb[tid]; }
    if (tid == 16) bsm[16] = vb[0];
    CP_WAIT0;
    __syncthreads();

    int wid = tid >> 5, lane = tid & 31;
    int r0 = wid * 16;

    unsigned bf[8][3][2];
    #pragma unroll
    for (int kt = 0; kt < 8; kt++) {
        int k0 = kt * 16;
        {
            int rr = ((lane >> 4) << 3) + (lane & 7);
            int cc = k0 + (((lane >> 3) & 1) << 3);
            unsigned t4[4];
            ldsm4(t4, Wh + rr * 136 + cc);
            bf[kt][0][0] = t4[0]; bf[kt][0][1] = t4[1];
            bf[kt][1][0] = t4[2]; bf[kt][1][1] = t4[3];
        }
        {
            int rr = 16 + ((lane >> 4) << 3) + (lane & 7);
            int cc = k0 + (((lane >> 3) & 1) << 3);
            unsigned t4[4];
            ldsm4(t4, Wh + rr * 136 + cc);
            bf[kt][2][0] = t4[0]; bf[kt][2][1] = t4[1];
        }
    }

    float accM[4], accL[4], accV[4];
    #pragma unroll
    for (int q = 0; q < 4; q++) { accM[q] = 0.f; accL[q] = 0.f; accV[q] = 0.f; }

    #pragma unroll
    for (int kt = 0; kt < 8; kt++) {
        int k0 = kt * 16;
        unsigned a[4], cfr[4];
        ldsm4(a,   Ha + (r0 + (lane & 15)) * 136 + k0 + ((lane >> 4) << 3));
        ldsm4(cfr, Hc + (r0 + (lane & 15)) * 136 + k0 + ((lane >> 4) << 3));
        mma16816(accM, a, bf[kt][0]);
        mma16816(accL, a, bf[kt][1]);
        mma16816(accV, cfr, bf[kt][2]);
    }

    int row = lane >> 2, c0 = 2 * (lane & 3);
    size_t gr0 = rowbase + r0 + row;
    size_t gr1 = gr0 + 8;
    *(float2*)(out + gr0 * 8 + c0) = make_float2(accM[0] + bsm[c0], accM[1] + bsm[c0 + 1]);
    *(float2*)(out + gr1 * 8 + c0) = make_float2(accM[2] + bsm[c0], accM[3] + bsm[c0 + 1]);
    float* outs = out + (size_t)NROW * 8;
    *(float2*)(outs + gr0 * 8 + c0) =
        make_float2(__expf(accL[0] + bsm[8 + c0]), __expf(accL[1] + bsm[8 + c0 + 1]));
    *(float2*)(outs + gr1 * 8 + c0) =
        make_float2(__expf(accL[2] + bsm[8 + c0]), __expf(accL[3] + bsm[8 + c0 + 1]));
    if ((lane & 3) == 0) {
        float* outv = out + (size_t)NROW * 16;
        outv[gr0] = accV[0] + bsm[16];
        outv[gr1] = accV[2] + bsm[16];
    }
}

// ---------------- launch ----------------
extern "C" void kernel_launch(void* const* d_in, const int* in_sizes, int n_in,
                              void* d_out, int out_size)
{
    const float* state  = (const float*)d_in[0];
    const int*   dones  = (const int*)d_in[1];
    const float* a_w1   = (const float*)d_in[2];
    const float* a_b1   = (const float*)d_in[3];
    const float* a_w2   = (const float*)d_in[4];
    const float* a_b2   = (const float*)d_in[5];
    const float* c_w1   = (const float*)d_in[6];
    const float* c_b1   = (const float*)d_in[7];
    const float* c_w2   = (const float*)d_in[8];
    const float* c_b2   = (const float*)d_in[9];
    const float* a_wih  = (const float*)d_in[10];
    const float* a_whh  = (const float*)d_in[11];
    const float* a_bih  = (const float*)d_in[12];
    const float* a_bhh  = (const float*)d_in[13];
    const float* c_wih  = (const float*)d_in[14];
    const float* c_whh  = (const float*)d_in[15];
    const float* c_bih  = (const float*)d_in[16];
    const float* c_bhh  = (const float*)d_in[17];
    const float* mean_w = (const float*)d_in[18];
    const float* mean_b = (const float*)d_in[19];
    const float* lstd_w = (const float*)d_in[20];
    const float* lstd_b = (const float*)d_in[21];
    const float* val_w  = (const float*)d_in[22];
    const float* val_b  = (const float*)d_in[23];

    cudaFuncSetAttribute(fg_kernel, cudaFuncAttributeMaxDynamicSharedMemorySize, FG_SMEM);
    cudaFuncSetAttribute(lstm_cluster_kernel, cudaFuncAttributeMaxDynamicSharedMemorySize, LSTM_SMEM);
    cudaFuncSetAttribute(heads_mma_kernel, cudaFuncAttributeMaxDynamicSharedMemorySize, HD_SMEM);

    pack16_kernel<<<512, 256>>>(a_wih, c_wih);

    dim3 fgg(1024, 2);
    fg_kernel<<<fgg, 256, FG_SMEM>>>(state,
                                     a_w1, a_b1, a_w2, a_b2,
                                     c_w1, c_b1, c_w2, c_b2,
                                     a_bih, a_bhh, c_bih, c_bhh);

    lstm_cluster_kernel<<<128, 256, LSTM_SMEM>>>(dones, a_whh, c_whh);

    heads_mma_kernel<<<1024, 256, HD_SMEM>>>(mean_w, mean_b, lstd_w, lstd_b,
                                             val_w, val_b, (float*)d_out);
}

// round 15
// speedup vs baseline: 1.5415x; 1.1438x over previous
#include <cuda_runtime.h>
#include <cuda_fp16.h>

// Problem dims
#define TT 512
#define BB 256
#define SS 64
#define HH 128
#define NROW (TT*BB)          // 131072

// ---------------- scratch (device globals; no allocation allowed) ----------------
__device__ __half g_gxh[(size_t)2 * NROW * 512];     // gx fp16 (268MB)
__device__ __half g_hh [(size_t)2 * NROW * HH];      // LSTM hidden outputs fp16 (67MB)
__device__ __half g_wih16[2 * 512 * 128];            // wih packed fp16

// ---------------- helpers ----------------
__device__ __forceinline__ float tanh_t(float x) {
    float y; asm("tanh.approx.f32 %0, %1;" : "=f"(y) : "f"(x)); return y;
}
__device__ __forceinline__ float sig_t(float x) {
    return fmaf(tanh_t(x * 0.5f), 0.5f, 0.5f);
}
__device__ __forceinline__ void mma16816(float* c, const unsigned* a, const unsigned* b) {
    asm volatile(
        "mma.sync.aligned.m16n8k16.row.col.f32.f16.f16.f32 "
        "{%0,%1,%2,%3}, {%4,%5,%6,%7}, {%8,%9}, {%0,%1,%2,%3};\n"
        : "+f"(c[0]), "+f"(c[1]), "+f"(c[2]), "+f"(c[3])
        : "r"(a[0]), "r"(a[1]), "r"(a[2]), "r"(a[3]), "r"(b[0]), "r"(b[1]));
}
__device__ __forceinline__ void ldsm4(unsigned* d, const __half* p) {
    unsigned addr = (unsigned)__cvta_generic_to_shared((void*)p);
    asm volatile("ldmatrix.sync.aligned.m8n8.x4.shared.b16 {%0,%1,%2,%3}, [%4];\n"
                 : "=r"(d[0]), "=r"(d[1]), "=r"(d[2]), "=r"(d[3]) : "r"(addr));
}
__device__ __forceinline__ void ldsm2(unsigned* d, const __half* p) {
    unsigned addr = (unsigned)__cvta_generic_to_shared((void*)p);
    asm volatile("ldmatrix.sync.aligned.m8n8.x2.shared.b16 {%0,%1}, [%2];\n"
                 : "=r"(d[0]), "=r"(d[1]) : "r"(addr));
}
__device__ __forceinline__ unsigned smem_u32(const void* p) {
    return (unsigned)__cvta_generic_to_shared((void*)p);
}
__device__ __forceinline__ void cpa16(void* smem_dst, const void* gsrc) {
    unsigned s = smem_u32(smem_dst);
    asm volatile("cp.async.cg.shared.global [%0], [%1], 16;" :: "r"(s), "l"(gsrc));
}
#define CP_COMMIT asm volatile("cp.async.commit_group;" ::: "memory")
#define CP_WAIT0  asm volatile("cp.async.wait_group 0;" ::: "memory")

__device__ __forceinline__ unsigned mapa_u32(unsigned addr, unsigned rank) {
    unsigned r;
    asm("mapa.shared::cluster.u32 %0, %1, %2;" : "=r"(r) : "r"(addr), "r"(rank));
    return r;
}
__device__ __forceinline__ void mbar_wait_acq_cluster(unsigned bar, unsigned parity) {
    asm volatile(
        "{\n\t.reg .pred P;\n"
        "W_%=:\n\t"
        "mbarrier.try_wait.parity.acquire.cluster.shared::cta.b64 P, [%0], %1;\n\t"
        "@P bra.uni D_%=;\n\t"
        "bra.uni W_%=;\n\t"
        "D_%=:\n\t}"
        :: "r"(bar), "r"(parity) : "memory");
}
__device__ __forceinline__ void mbar_arrive_rel_cluster(unsigned rem_bar) {
    asm volatile("mbarrier.arrive.release.cluster.shared::cluster.b64 _, [%0];"
                 :: "r"(rem_bar) : "memory");
}
__device__ __forceinline__ void st_cluster_u32(unsigned addr, unsigned v) {
    asm volatile("st.shared::cluster.b32 [%0], %1;" :: "r"(addr), "r"(v) : "memory");
}

// ---------------- pack wih -> fp16 ----------------
__global__ void pack16_kernel(const float* __restrict__ a_wih, const float* __restrict__ c_wih) {
    int idx = blockIdx.x * blockDim.x + threadIdx.x;
    if (idx >= 2 * 65536) return;
    int net = idx >> 16, r = idx & 65535;
    g_wih16[idx] = __float2half((net ? c_wih : a_wih)[r]);
}

// =====================================================================
// Fused feature kernel (exact R8): f2 = relu(relu(X@W1.T+b1)@W2.T+b2),
// then gx = f2 @ wih.T + (bih+bhh). launch_bounds(256,2) -> 2 CTA/SM.
// =====================================================================
#define XS_STR 72
#define MH_STR 136
#define FG_BS  0
#define FG_XS  3072
#define FG_W1S 21504
#define FG_W2S 39936
#define FG_C1S 74752
#define FG_SMEM 109568

__global__ void __launch_bounds__(256, 2) fg_kernel(
    const float* __restrict__ x,
    const float* __restrict__ a_w1, const float* __restrict__ a_b1,
    const float* __restrict__ a_w2, const float* __restrict__ a_b2,
    const float* __restrict__ c_w1, const float* __restrict__ c_b1,
    const float* __restrict__ c_w2, const float* __restrict__ c_b2,
    const float* __restrict__ a_bih, const float* __restrict__ a_bhh,
    const float* __restrict__ c_bih, const float* __restrict__ c_bhh)
{
    extern __shared__ __align__(16) char smraw[];
    float*  bs1  = (float*)(smraw + FG_BS);        // 128
    float*  bs2  = bs1 + 128;                      // 128
    float*  bsum = bs2 + 128;                      // 512
    __half* Xs   = (__half*)(smraw + FG_XS);       // stride 72
    __half* W1s  = (__half*)(smraw + FG_W1S);      // stride 72
    __half* W2s  = (__half*)(smraw + FG_W2S);      // stride 136
    __half* C1s  = (__half*)(smraw + FG_C1S);      // stride 136
    __half* F2s  = (__half*)(smraw + FG_XS);       // stride 136 (overlays Xs+W1s)
    __half* Wb[2]; Wb[0] = W2s; Wb[1] = C1s;

    int tid = threadIdx.x;
    int net = blockIdx.y;
    size_t rowbase = (size_t)blockIdx.x * 128;

    const float* w1 = net ? c_w1 : a_w1;
    const float* b1 = net ? c_b1 : a_b1;
    const float* w2 = net ? c_w2 : a_w2;
    const float* b2 = net ? c_b2 : a_b2;
    const float* bih = net ? c_bih : a_bih;
    const float* bhh = net ? c_bhh : a_bhh;

    {   // X [128][64]
        const float4* xg = (const float4*)(x + rowbase * SS);
        for (int i = tid; i < 128 * 16; i += 256) {
            int r = i >> 4, c4 = i & 15;
            float4 v = xg[(size_t)r * 16 + c4];
            *(__half2*)&Xs[r * XS_STR + c4 * 4]     = __floats2half2_rn(v.x, v.y);
            *(__half2*)&Xs[r * XS_STR + c4 * 4 + 2] = __floats2half2_rn(v.z, v.w);
        }
    }
    {   // W1 [128][64]
        const float4* wg = (const float4*)w1;
        for (int i = tid; i < 128 * 16; i += 256) {
            int r = i >> 4, c4 = i & 15;
            float4 v = wg[(size_t)r * 16 + c4];
            *(__half2*)&W1s[r * XS_STR + c4 * 4]     = __floats2half2_rn(v.x, v.y);
            *(__half2*)&W1s[r * XS_STR + c4 * 4 + 2] = __floats2half2_rn(v.z, v.w);
        }
    }
    {   // W2 [128][128]
        const float4* wg = (const float4*)w2;
        for (int i = tid; i < 128 * 32; i += 256) {
            int r = i >> 5, c4 = i & 31;
            float4 v = wg[(size_t)r * 32 + c4];
            *(__half2*)&W2s[r * MH_STR + c4 * 4]     = __floats2half2_rn(v.x, v.y);
            *(__half2*)&W2s[r * MH_STR + c4 * 4 + 2] = __floats2half2_rn(v.z, v.w);
        }
    }
    if (tid < 128) { bs1[tid] = __ldg(b1 + tid); bs2[tid] = __ldg(b2 + tid); }
    for (int i = tid; i < 512; i += 256) bsum[i] = __ldg(bih + i) + __ldg(bhh + i);
    __syncthreads();

    int wid = tid >> 5, lane = tid & 31;
    int warp_m = wid & 3, warp_n = wid >> 2;
    int m_base = warp_m * 32, n_base = warp_n * 64;

    float acc[2][8][4];

    // -------- stage A: C1 = relu(X @ W1.T + b1), K=64 --------
    #pragma unroll
    for (int mt = 0; mt < 2; mt++)
        #pragma unroll
        for (int nt = 0; nt < 8; nt++)
            #pragma unroll
            for (int q = 0; q < 4; q++) acc[mt][nt][q] = 0.f;

    #pragma unroll
    for (int kt = 0; kt < 4; kt++) {
        int k0 = kt * 16;
        unsigned a[2][4], b[8][2];
        #pragma unroll
        for (int mt = 0; mt < 2; mt++) {
            int r = m_base + mt * 16 + (lane & 15);
            int c = k0 + ((lane >> 4) << 3);
            ldsm4(a[mt], Xs + r * XS_STR + c);
        }
        #pragma unroll
        for (int np = 0; np < 4; np++) {
            int n0 = n_base + np * 16;
            int rr = n0 + ((lane >> 4) << 3) + (lane & 7);
            int cc = k0 + (((lane >> 3) & 1) << 3);
            unsigned t4[4];
            ldsm4(t4, W1s + rr * XS_STR + cc);
            b[np * 2][0] = t4[0]; b[np * 2][1] = t4[1];
            b[np * 2 + 1][0] = t4[2]; b[np * 2 + 1][1] = t4[3];
        }
        #pragma unroll
        for (int mt = 0; mt < 2; mt++)
            #pragma unroll
            for (int nt = 0; nt < 8; nt++)
                mma16816(acc[mt][nt], a[mt], b[nt]);
    }
    #pragma unroll
    for (int mt = 0; mt < 2; mt++) {
        #pragma unroll
        for (int nt = 0; nt < 8; nt++) {
            int r = m_base + mt * 16 + (lane >> 2);
            int c = n_base + nt * 8 + 2 * (lane & 3);
            float v0 = fmaxf(acc[mt][nt][0] + bs1[c], 0.f);
            float v1 = fmaxf(acc[mt][nt][1] + bs1[c + 1], 0.f);
            float v2 = fmaxf(acc[mt][nt][2] + bs1[c], 0.f);
            float v3 = fmaxf(acc[mt][nt][3] + bs1[c + 1], 0.f);
            *(__half2*)&C1s[r * MH_STR + c]       = __floats2half2_rn(v0, v1);
            *(__half2*)&C1s[(r + 8) * MH_STR + c] = __floats2half2_rn(v2, v3);
        }
    }
    __syncthreads();

    // -------- stage B: F2 = relu(C1 @ W2.T + b2), K=128 --------
    #pragma unroll
    for (int mt = 0; mt < 2; mt++)
        #pragma unroll
        for (int nt = 0; nt < 8; nt++)
            #pragma unroll
            for (int q = 0; q < 4; q++) acc[mt][nt][q] = 0.f;

    #pragma unroll
    for (int kt = 0; kt < 8; kt++) {
        int k0 = kt * 16;
        unsigned a[2][4], b[8][2];
        #pragma unroll
        for (int mt = 0; mt < 2; mt++) {
            int r = m_base + mt * 16 + (lane & 15);
            int c = k0 + ((lane >> 4) << 3);
            ldsm4(a[mt], C1s + r * MH_STR + c);
        }
        #pragma unroll
        for (int np = 0; np < 4; np++) {
            int n0 = n_base + np * 16;
            int rr = n0 + ((lane >> 4) << 3) + (lane & 7);
            int cc = k0 + (((lane >> 3) & 1) << 3);
            unsigned t4[4];
            ldsm4(t4, W2s + rr * MH_STR + cc);
            b[np * 2][0] = t4[0]; b[np * 2][1] = t4[1];
            b[np * 2 + 1][0] = t4[2]; b[np * 2 + 1][1] = t4[3];
        }
        #pragma unroll
        for (int mt = 0; mt < 2; mt++)
            #pragma unroll
            for (int nt = 0; nt < 8; nt++)
                mma16816(acc[mt][nt], a[mt], b[nt]);
    }
    // epilogue B -> F2s
    #pragma unroll
    for (int mt = 0; mt < 2; mt++) {
        #pragma unroll
        for (int nt = 0; nt < 8; nt++) {
            int r = m_base + mt * 16 + (lane >> 2);
            int c = n_base + nt * 8 + 2 * (lane & 3);
            float v0 = fmaxf(acc[mt][nt][0] + bs2[c], 0.f);
            float v1 = fmaxf(acc[mt][nt][1] + bs2[c + 1], 0.f);
            float v2 = fmaxf(acc[mt][nt][2] + bs2[c], 0.f);
            float v3 = fmaxf(acc[mt][nt][3] + bs2[c + 1], 0.f);
            *(__half2*)&F2s[r * MH_STR + c]       = __floats2half2_rn(v0, v1);
            *(__half2*)&F2s[(r + 8) * MH_STR + c] = __floats2half2_rn(v2, v3);
        }
    }
    __syncthreads();

    // -------- gx phase: loop 4 weight chunks; A re-ldsm'd from F2s --------
    const __half* wsrc = g_wih16 + (size_t)net * 65536;

    for (int i = tid; i < 2048; i += 256) {
        int r = i >> 4, c = i & 15;
        cpa16(Wb[0] + r * MH_STR + c * 8, wsrc + r * 128 + c * 8);
    }
    CP_COMMIT;
    CP_WAIT0;
    __syncthreads();

    __half* outp = g_gxh + (size_t)net * NROW * 512;

    #pragma unroll
    for (int ch = 0; ch < 4; ch++) {
        if (ch < 3) {
            const __half* src = wsrc + (ch + 1) * 128 * 128;
            __half* dst = Wb[(ch + 1) & 1];
            for (int i = tid; i < 2048; i += 256) {
                int r = i >> 4, c = i & 15;
                cpa16(dst + r * MH_STR + c * 8, src + r * 128 + c * 8);
            }
            CP_COMMIT;
        }
        const __half* Ws = Wb[ch & 1];

        #pragma unroll
        for (int mt = 0; mt < 2; mt++)
            #pragma unroll
            for (int nt = 0; nt < 8; nt++)
                #pragma unroll
                for (int q = 0; q < 4; q++) acc[mt][nt][q] = 0.f;

        #pragma unroll
        for (int kt = 0; kt < 8; kt++) {
            int k0 = kt * 16;
            unsigned a[2][4], b[8][2];
            #pragma unroll
            for (int mt = 0; mt < 2; mt++) {
                int r = m_base + mt * 16 + (lane & 15);
                int c = k0 + ((lane >> 4) << 3);
                ldsm4(a[mt], F2s + r * MH_STR + c);
            }
            #pragma unroll
            for (int np = 0; np < 4; np++) {
                int n0 = n_base + np * 16;
                int rr = n0 + ((lane >> 4) << 3) + (lane & 7);
                int cc = k0 + (((lane >> 3) & 1) << 3);
                unsigned t4[4];
                ldsm4(t4, Ws + rr * MH_STR + cc);
                b[np * 2][0] = t4[0]; b[np * 2][1] = t4[1];
                b[np * 2 + 1][0] = t4[2]; b[np * 2 + 1][1] = t4[3];
            }
            #pragma unroll
            for (int mt = 0; mt < 2; mt++)
                #pragma unroll
                for (int nt = 0; nt < 8; nt++)
                    mma16816(acc[mt][nt], a[mt], b[nt]);
        }
        #pragma unroll
        for (int mt = 0; mt < 2; mt++) {
            #pragma unroll
            for (int nt = 0; nt < 8; nt++) {
                int r = m_base + mt * 16 + (lane >> 2);
                int c = n_base + nt * 8 + 2 * (lane & 3);
                int gc = ch * 128 + c;
                float v0 = acc[mt][nt][0] + bsum[gc];
                float v1 = acc[mt][nt][1] + bsum[gc + 1];
                float v2 = acc[mt][nt][2] + bsum[gc];
                float v3 = acc[mt][nt][3] + bsum[gc + 1];
                *(__half2*)(outp + (rowbase + r) * (size_t)512 + gc) = __floats2half2_rn(v0, v1);
                *(__half2*)(outp + (rowbase + r + 8) * (size_t)512 + gc) = __floats2half2_rn(v2, v3);
            }
        }
        if (ch < 3) {
            CP_WAIT0;
            __syncthreads();
        }
    }
}

// =====================================================================
// LSTM recurrence, TRANSPOSED formulation, cluster-pair j-split.
// gatesT[256][8] = Wp[256][128] @ h^T : M=outputs (no pad), N=batch=8.
// M-permutation: m = 32w + gate*8 + s  (s = lane>>2), jl = 8w + s.
// Thread owns all 4 gates for ONE jl x 2 batch rows (bA=2*(lane&3), bB).
// Pair-shuffle epilogue: threads (lane, lane^4) own adjacent jl; one
// shfl.xor(4) lets even-s store the half2 {h(jl),h(jl+1)} for row bA and
// odd-s for row bB -> ONE b32 DSMEM push per thread (R8-proven inst).
// Per warp per step: 8 ldsm.x2 (h) + 16 mma. Wp frags hoisted (64 regs).
// smem (bytes):
//   Ws   [256][136] half  0     .. 69632
//   hbuf [2][8][136] half 69632 .. 73984
//   gxs  [2][8][264] half 73984 .. 82432
//   maskb[512] u32        82432 .. 84480
//   mbars[2] u64          84480 .. 84496
// =====================================================================
#define LW_WS  0
#define LW_HB  69632
#define LW_GX  73984
#define LW_MB  82432
#define LW_BAR 84480
#define LSTM_SMEM 84512

__global__ void __launch_bounds__(256) __cluster_dims__(2, 1, 1)
lstm_cluster_kernel(const int* __restrict__ dones,
                    const float* __restrict__ a_whh, const float* __restrict__ c_whh)
{
    extern __shared__ __align__(16) char sm[];
    __half*   Ws    = (__half*)(sm + LW_WS);
    __half*   hbuf  = (__half*)(sm + LW_HB);
    __half*   gxs   = (__half*)(sm + LW_GX);
    unsigned* maskb = (unsigned*)(sm + LW_MB);

    int tid = threadIdx.x;
    int bx  = blockIdx.x;
    int net = bx >> 6;
    int rowgroup = (bx >> 1) & 31;
    int rb = rowgroup << 3;                       // first of 8 batch rows
    unsigned rank;
    asm("mov.u32 %0, %%cluster_ctarank;" : "=r"(rank));
    unsigned peer = rank ^ 1u;
    int jbase = (int)rank * 64;
    const float* whh = net ? c_whh : a_whh;

    // ---- permuted Wp rows: m -> w=m>>5, offs=m&31, gate=offs>>3, jl=8w+(offs&7) ----
    for (int i = tid; i < 256 * 32; i += 256) {
        int m = i >> 5, c4 = i & 31;
        int w  = m >> 5;
        int offs = m & 31;
        int g  = offs >> 3;
        int jl = (w << 3) + (offs & 7);
        int orig = g * 128 + jbase + jl;
        float4 v = ((const float4*)whh)[orig * 32 + c4];
        *(__half2*)&Ws[m * 136 + c4 * 4]     = __floats2half2_rn(v.x, v.y);
        *(__half2*)&Ws[m * 136 + c4 * 4 + 2] = __floats2half2_rn(v.z, v.w);
    }
    for (int i = tid; i < 2 * 8 * 136; i += 256) hbuf[i] = __float2half(0.f);
    for (int s = tid; s < 512; s += 256) {
        unsigned b = 0;
        #pragma unroll
        for (int r = 0; r < 8; r++) b |= ((unsigned)dones[s * 256 + rb + r] & 1u) << r;
        maskb[s] = b;
    }
    const __half* gxg = g_gxh + (size_t)net * NROW * 512;
    {   // gx(0): gxs[row][seg*64+u] = gx[row][seg*128 + jbase + u]
        int row = tid >> 5, rem = tid & 31, seg = rem >> 3, q = rem & 7;
        uint4 v = *(const uint4*)(gxg + (size_t)(rb + row) * 512 + seg * 128 + jbase + q * 8);
        ((uint4*)gxs)[33 * row + 8 * seg + q] = v;
    }
    unsigned barL0 = smem_u32(sm + LW_BAR);
    unsigned barL1 = barL0 + 8;
    if (tid == 0) {
        asm volatile("mbarrier.init.shared.b64 [%0], %1;" :: "r"(barL0), "r"(256u));
        asm volatile("mbarrier.init.shared.b64 [%0], %1;" :: "r"(barL1), "r"(256u));
    }
    __syncthreads();
    asm volatile("barrier.cluster.arrive.aligned;" ::: "memory");
    asm volatile("barrier.cluster.wait.aligned;" ::: "memory");

    unsigned remBar[2];
    remBar[0] = mapa_u32(barL0, peer);
    remBar[1] = mapa_u32(barL1, peer);

    int lane = tid & 31, wid = tid >> 5;

    // hoist Wp A fragments: 2 mtiles x 8 kt x 4 regs (m rows [32w, 32w+32))
    unsigned afr[2][8][4];
    #pragma unroll
    for (int mt = 0; mt < 2; mt++)
        #pragma unroll
        for (int kt = 0; kt < 8; kt++) {
            int r = 32 * wid + mt * 16 + (lane & 15);
            int c = kt * 16 + ((lane >> 4) << 3);
            ldsm4(afr[mt][kt], Ws + r * 136 + c);
        }

    int s  = lane >> 2;            // 0..7
    int jl = 8 * wid + s;          // this thread's local hidden col
    int bA = 2 * (lane & 3);       // batch rows
    int bB = bA + 1;
    bool leftT = ((s & 1) == 0);   // pair role: left stores row bA, right row bB
    int rowSt = leftT ? bA : bB;
    int colSt = leftT ? jl : (jl - 1);   // even in both cases -> 4B aligned

    // remote b32 push addresses for both hbuf ping-pong buffers
    unsigned remH[2];
    {
        unsigned base = smem_u32(hbuf);
        #pragma unroll
        for (int buf = 0; buf < 2; buf++)
            remH[buf] = mapa_u32(base + (unsigned)(((buf * 8 + rowSt) * 136 + jbase + colSt) * 2), peer);
    }

    float cstA = 0.f, cstB = 0.f;
    __half* hog = g_hh + (size_t)net * NROW * HH;
    int ph0 = 0, ph1 = 0;

    for (int t = 0; t < TT; t++) {
        bool haveNext = (t < TT - 1);
        uint4 pf;
        if (haveNext) {
            int prow = tid >> 5, rem = tid & 31, seg = rem >> 3, q = rem & 7;
            pf = *(const uint4*)(gxg + (size_t)((t + 1) * 256 + rb + prow) * 512
                                 + seg * 128 + jbase + q * 8);
        }
        if (t > 0) {
            if ((t - 1) & 1) { mbar_wait_acq_cluster(barL1, (unsigned)ph1); ph1 ^= 1; }
            else             { mbar_wait_acq_cluster(barL0, (unsigned)ph0); ph0 ^= 1; }
        }

        // B fragments from h (8 batch rows x 128 cols), shared by both mtiles
        const __half* hb = hbuf + (t & 1) * (8 * 136);
        unsigned B[8][2];
        #pragma unroll
        for (int kt = 0; kt < 8; kt++)
            ldsm2(B[kt], hb + (lane & 7) * 136 + kt * 16 + (((lane >> 3) & 1) << 3));

        float acc[2][4];
        #pragma unroll
        for (int mt = 0; mt < 2; mt++)
            #pragma unroll
            for (int q = 0; q < 4; q++) acc[mt][q] = 0.f;

        #pragma unroll
        for (int kt = 0; kt < 8; kt++) {
            mma16816(acc[0], afr[0][kt], B[kt]);
            mma16816(acc[1], afr[1][kt], B[kt]);
        }
        // acc[0][0/1] = gate i (bA/bB); acc[0][2/3] = gate f;
        // acc[1][0/1] = gate g;         acc[1][2/3] = gate o.

        // ---- register epilogue (pair-shuffle b32 stores) ----
        {
            const __half* gxcur = gxs + (t & 1) * 2112;
            float giA = __half2float(gxcur[bA * 264 + jl]);
            float giB = __half2float(gxcur[bB * 264 + jl]);
            float gfA = __half2float(gxcur[bA * 264 + 64 + jl]);
            float gfB = __half2float(gxcur[bB * 264 + 64 + jl]);
            float ggA = __half2float(gxcur[bA * 264 + 128 + jl]);
            float ggB = __half2float(gxcur[bB * 264 + 128 + jl]);
            float goA = __half2float(gxcur[bA * 264 + 192 + jl]);
            float goB = __half2float(gxcur[bB * 264 + 192 + jl]);

            float iA = sig_t(acc[0][0] + giA), iB = sig_t(acc[0][1] + giB);
            float fA = sig_t(acc[0][2] + gfA), fB = sig_t(acc[0][3] + gfB);
            float gA = tanh_t(acc[1][0] + ggA), gB = tanh_t(acc[1][1] + ggB);
            float oA = sig_t(acc[1][2] + goA), oB = sig_t(acc[1][3] + goB);

            float c2A = fA * cstA + iA * gA;
            float c2B = fB * cstB + iB * gB;
            float h2A = oA * tanh_t(c2A);
            float h2B = oB * tanh_t(c2B);

            unsigned bits = maskb[t];
            float mA = ((bits >> bA) & 1u) ? 0.f : 1.f;
            float mB = ((bits >> bB) & 1u) ? 0.f : 1.f;
            cstA = c2A * mA;
            cstB = c2B * mB;

            // pack {rowA, rowB} halves; exchange with jl-neighbor (lane^4)
            unsigned pkm = (unsigned)__half_as_ushort(__float2half(h2A * mA))
                         | ((unsigned)__half_as_ushort(__float2half(h2B * mB)) << 16);
            unsigned pku = (unsigned)__half_as_ushort(__float2half(h2A))
                         | ((unsigned)__half_as_ushort(__float2half(h2B)) << 16);
            unsigned otm = __shfl_xor_sync(0xffffffffu, pkm, 4);
            unsigned otu = __shfl_xor_sync(0xffffffffu, pku, 4);
            // left: row bA cols {jl, jl+1}; right: row bB cols {jl-1, jl}
            unsigned vm = leftT ? ((pkm & 0xFFFFu) | (otm << 16))
                                : ((otm >> 16) | (pkm & 0xFFFF0000u));
            unsigned vu = leftT ? ((pku & 0xFFFFu) | (otu << 16))
                                : ((otu >> 16) | (pku & 0xFFFF0000u));

            if (haveNext) {
                int nb = (t + 1) & 1;
                // remote b32 push ASAP (in flight during rest of epilogue)
                st_cluster_u32(remH[nb], vm);
                // local store (same layout)
                *(unsigned*)&hbuf[(nb * 8 + rowSt) * 136 + jbase + colSt] = vm;
                {
                    int prow = tid >> 5, rem = tid & 31, seg = rem >> 3, q = rem & 7;
                    ((uint4*)(gxs + nb * 2112))[33 * prow + 8 * seg + q] = pf;
                }
                // per-thread release-arrive on peer barrier (R8-proven)
                mbar_arrive_rel_cluster(remBar[t & 1]);
            }
            *(unsigned*)(hog + (size_t)(t * 256 + rb + rowSt) * HH + jbase + colSt) = vu;
        }
        __syncthreads();
    }

    asm volatile("barrier.cluster.arrive.aligned;" ::: "memory");
    asm volatile("barrier.cluster.wait.aligned;" ::: "memory");
}

// =====================================================================
// Heads on HMMA (exact R8)
// =====================================================================
#define HD_HA 0
#define HD_HC 34816
#define HD_W  69632
#define HD_B  78336
#define HD_SMEM 78464

__global__ void __launch_bounds__(256) heads_mma_kernel(
    const float* __restrict__ mw, const float* __restrict__ mb,
    const float* __restrict__ lw, const float* __restrict__ lb,
    const float* __restrict__ vw, const float* __restrict__ vb,
    float* __restrict__ out)
{
    extern __shared__ __align__(16) char sm[];
    __half* Ha = (__half*)(sm + HD_HA);   // [128][136]
    __half* Hc = (__half*)(sm + HD_HC);   // [128][136]
    __half* Wh = (__half*)(sm + HD_W);    // [32][136]
    float*  bsm = (float*)(sm + HD_B);

    int tid = threadIdx.x;
    size_t rowbase = (size_t)blockIdx.x * 128;

    const __half* ha = g_hh + rowbase * HH;
    const __half* hc = g_hh + (size_t)NROW * HH + rowbase * HH;
    for (int i = tid; i < 2048; i += 256) {
        int r = i >> 4, c = i & 15;
        cpa16(Ha + r * 136 + c * 8, ha + (size_t)r * HH + c * 8);
        cpa16(Hc + r * 136 + c * 8, hc + (size_t)r * HH + c * 8);
    }
    CP_COMMIT;
    for (int i = tid; i < 4096; i += 256) {
        int r = i >> 7, c = i & 127;
        float v = 0.f;
        if (r < 8) v = mw[r * 128 + c];
        else if (r < 16) v = lw[(r - 8) * 128 + c];
        else if (r == 16) v = vw[c];
        Wh[r * 136 + c] = __float2half(v);
    }
    if (tid < 8) { bsm[tid] = mb[tid]; bsm[8 + tid] = lb[tid]; }
    if (tid == 16) bsm[16] = vb[0];
    CP_WAIT0;
    __syncthreads();

    int wid = tid >> 5, lane = tid & 31;
    int r0 = wid * 16;

    unsigned bf[8][3][2];
    #pragma unroll
    for (int kt = 0; kt < 8; kt++) {
        int k0 = kt * 16;
        {
            int rr = ((lane >> 4) << 3) + (lane & 7);
            int cc = k0 + (((lane >> 3) & 1) << 3);
            unsigned t4[4];
            ldsm4(t4, Wh + rr * 136 + cc);
            bf[kt][0][0] = t4[0]; bf[kt][0][1] = t4[1];
            bf[kt][1][0] = t4[2]; bf[kt][1][1] = t4[3];
        }
        {
            int rr = 16 + ((lane >> 4) << 3) + (lane & 7);
            int cc = k0 + (((lane >> 3) & 1) << 3);
            unsigned t4[4];
            ldsm4(t4, Wh + rr * 136 + cc);
            bf[kt][2][0] = t4[0]; bf[kt][2][1] = t4[1];
        }
    }

    float accM[4], accL[4], accV[4];
    #pragma unroll
    for (int q = 0; q < 4; q++) { accM[q] = 0.f; accL[q] = 0.f; accV[q] = 0.f; }

    #pragma unroll
    for (int kt = 0; kt < 8; kt++) {
        int k0 = kt * 16;
        unsigned a[4], cfr[4];
        ldsm4(a,   Ha + (r0 + (lane & 15)) * 136 + k0 + ((lane >> 4) << 3));
        ldsm4(cfr, Hc + (r0 + (lane & 15)) * 136 + k0 + ((lane >> 4) << 3));
        mma16816(accM, a, bf[kt][0]);
        mma16816(accL, a, bf[kt][1]);
        mma16816(accV, cfr, bf[kt][2]);
    }

    int row = lane >> 2, c0 = 2 * (lane & 3);
    size_t gr0 = rowbase + r0 + row;
    size_t gr1 = gr0 + 8;
    *(float2*)(out + gr0 * 8 + c0) = make_float2(accM[0] + bsm[c0], accM[1] + bsm[c0 + 1]);
    *(float2*)(out + gr1 * 8 + c0) = make_float2(accM[2] + bsm[c0], accM[3] + bsm[c0 + 1]);
    float* outs = out + (size_t)NROW * 8;
    *(float2*)(outs + gr0 * 8 + c0) =
        make_float2(__expf(accL[0] + bsm[8 + c0]), __expf(accL[1] + bsm[8 + c0 + 1]));
    *(float2*)(outs + gr1 * 8 + c0) =
        make_float2(__expf(accL[2] + bsm[8 + c0]), __expf(accL[3] + bsm[8 + c0 + 1]));
    if ((lane & 3) == 0) {
        float* outv = out + (size_t)NROW * 16;
        outv[gr0] = accV[0] + bsm[16];
        outv[gr1] = accV[2] + bsm[16];
    }
}

// ---------------- launch ----------------
extern "C" void kernel_launch(void* const* d_in, const int* in_sizes, int n_in,
                              void* d_out, int out_size)
{
    const float* state  = (const float*)d_in[0];
    const int*   dones  = (const int*)d_in[1];
    const float* a_w1   = (const float*)d_in[2];
    const float* a_b1   = (const float*)d_in[3];
    const float* a_w2   = (const float*)d_in[4];
    const float* a_b2   = (const float*)d_in[5];
    const float* c_w1   = (const float*)d_in[6];
    const float* c_b1   = (const float*)d_in[7];
    const float* c_w2   = (const float*)d_in[8];
    const float* c_b2   = (const float*)d_in[9];
    const float* a_wih  = (const float*)d_in[10];
    const float* a_whh  = (const float*)d_in[11];
    const float* a_bih  = (const float*)d_in[12];
    const float* a_bhh  = (const float*)d_in[13];
    const float* c_wih  = (const float*)d_in[14];
    const float* c_whh  = (const float*)d_in[15];
    const float* c_bih  = (const float*)d_in[16];
    const float* c_bhh  = (const float*)d_in[17];
    const float* mean_w = (const float*)d_in[18];
    const float* mean_b = (const float*)d_in[19];
    const float* lstd_w = (const float*)d_in[20];
    const float* lstd_b = (const float*)d_in[21];
    const float* val_w  = (const float*)d_in[22];
    const float* val_b  = (const float*)d_in[23];

    cudaFuncSetAttribute(fg_kernel, cudaFuncAttributeMaxDynamicSharedMemorySize, FG_SMEM);
    cudaFuncSetAttribute(lstm_cluster_kernel, cudaFuncAttributeMaxDynamicSharedMemorySize, LSTM_SMEM);
    cudaFuncSetAttribute(heads_mma_kernel, cudaFuncAttributeMaxDynamicSharedMemorySize, HD_SMEM);

    pack16_kernel<<<512, 256>>>(a_wih, c_wih);

    dim3 fgg(1024, 2);
    fg_kernel<<<fgg, 256, FG_SMEM>>>(state,
                                     a_w1, a_b1, a_w2, a_b2,
                                     c_w1, c_b1, c_w2, c_b2,
                                     a_bih, a_bhh, c_bih, c_bhh);

    lstm_cluster_kernel<<<128, 256, LSTM_SMEM>>>(dones, a_whh, c_whh);

    heads_mma_kernel<<<1024, 256, HD_SMEM>>>(mean_w, mean_b, lstd_w, lstd_b,
                                             val_w, val_b, (float*)d_out);
}

// round 16
// speedup vs baseline: 1.5457x; 1.0027x over previous
#include <cuda_runtime.h>
#include <cuda_fp16.h>

// Problem dims
#define TT 512
#define BB 256
#define SS 64
#define HH 128
#define NROW (TT*BB)          // 131072

// ---------------- scratch (device globals; no allocation allowed) ----------------
__device__ __half g_gxh[(size_t)2 * NROW * 512];     // gx fp16 (268MB)
__device__ __half g_hh [(size_t)2 * NROW * HH];      // LSTM hidden outputs fp16 (67MB)
__device__ __half g_wih16[2 * 512 * 128];            // wih packed fp16

// ---------------- helpers ----------------
__device__ __forceinline__ float tanh_t(float x) {
    float y; asm("tanh.approx.f32 %0, %1;" : "=f"(y) : "f"(x)); return y;
}
__device__ __forceinline__ float sig_t(float x) {
    return fmaf(tanh_t(x * 0.5f), 0.5f, 0.5f);
}
__device__ __forceinline__ void mma16816(float* c, const unsigned* a, const unsigned* b) {
    asm volatile(
        "mma.sync.aligned.m16n8k16.row.col.f32.f16.f16.f32 "
        "{%0,%1,%2,%3}, {%4,%5,%6,%7}, {%8,%9}, {%0,%1,%2,%3};\n"
        : "+f"(c[0]), "+f"(c[1]), "+f"(c[2]), "+f"(c[3])
        : "r"(a[0]), "r"(a[1]), "r"(a[2]), "r"(a[3]), "r"(b[0]), "r"(b[1]));
}
__device__ __forceinline__ void ldsm4(unsigned* d, const __half* p) {
    unsigned addr = (unsigned)__cvta_generic_to_shared((void*)p);
    asm volatile("ldmatrix.sync.aligned.m8n8.x4.shared.b16 {%0,%1,%2,%3}, [%4];\n"
                 : "=r"(d[0]), "=r"(d[1]), "=r"(d[2]), "=r"(d[3]) : "r"(addr));
}
__device__ __forceinline__ void ldsm2(unsigned* d, const __half* p) {
    unsigned addr = (unsigned)__cvta_generic_to_shared((void*)p);
    asm volatile("ldmatrix.sync.aligned.m8n8.x2.shared.b16 {%0,%1}, [%2];\n"
                 : "=r"(d[0]), "=r"(d[1]) : "r"(addr));
}
__device__ __forceinline__ unsigned smem_u32(const void* p) {
    return (unsigned)__cvta_generic_to_shared((void*)p);
}
__device__ __forceinline__ void cpa16(void* smem_dst, const void* gsrc) {
    unsigned s = smem_u32(smem_dst);
    asm volatile("cp.async.cg.shared.global [%0], [%1], 16;" :: "r"(s), "l"(gsrc));
}
#define CP_COMMIT asm volatile("cp.async.commit_group;" ::: "memory")
#define CP_WAIT0  asm volatile("cp.async.wait_group 0;" ::: "memory")

__device__ __forceinline__ unsigned mapa_u32(unsigned addr, unsigned rank) {
    unsigned r;
    asm("mapa.shared::cluster.u32 %0, %1, %2;" : "=r"(r) : "r"(addr), "r"(rank));
    return r;
}
__device__ __forceinline__ void mbar_wait_acq_cluster(unsigned bar, unsigned parity) {
    asm volatile(
        "{\n\t.reg .pred P;\n"
        "W_%=:\n\t"
        "mbarrier.try_wait.parity.acquire.cluster.shared::cta.b64 P, [%0], %1;\n\t"
        "@P bra.uni D_%=;\n\t"
        "bra.uni W_%=;\n\t"
        "D_%=:\n\t}"
        :: "r"(bar), "r"(parity) : "memory");
}
__device__ __forceinline__ void mbar_arrive_rel_cluster(unsigned rem_bar) {
    asm volatile("mbarrier.arrive.release.cluster.shared::cluster.b64 _, [%0];"
                 :: "r"(rem_bar) : "memory");
}
__device__ __forceinline__ void st_cluster_u32(unsigned addr, unsigned v) {
    asm volatile("st.shared::cluster.b32 [%0], %1;" :: "r"(addr), "r"(v) : "memory");
}

// ---------------- pack wih -> fp16 ----------------
__global__ void pack16_kernel(const float* __restrict__ a_wih, const float* __restrict__ c_wih) {
    int idx = blockIdx.x * blockDim.x + threadIdx.x;
    if (idx >= 2 * 65536) return;
    int net = idx >> 16, r = idx & 65535;
    g_wih16[idx] = __float2half((net ? c_wih : a_wih)[r]);
}

// =====================================================================
// Fused feature kernel (exact R8): f2 = relu(relu(X@W1.T+b1)@W2.T+b2),
// then gx = f2 @ wih.T + (bih+bhh). launch_bounds(256,2) -> 2 CTA/SM.
// =====================================================================
#define XS_STR 72
#define MH_STR 136
#define FG_BS  0
#define FG_XS  3072
#define FG_W1S 21504
#define FG_W2S 39936
#define FG_C1S 74752
#define FG_SMEM 109568

__global__ void __launch_bounds__(256, 2) fg_kernel(
    const float* __restrict__ x,
    const float* __restrict__ a_w1, const float* __restrict__ a_b1,
    const float* __restrict__ a_w2, const float* __restrict__ a_b2,
    const float* __restrict__ c_w1, const float* __restrict__ c_b1,
    const float* __restrict__ c_w2, const float* __restrict__ c_b2,
    const float* __restrict__ a_bih, const float* __restrict__ a_bhh,
    const float* __restrict__ c_bih, const float* __restrict__ c_bhh)
{
    extern __shared__ __align__(16) char smraw[];
    float*  bs1  = (float*)(smraw + FG_BS);        // 128
    float*  bs2  = bs1 + 128;                      // 128
    float*  bsum = bs2 + 128;                      // 512
    __half* Xs   = (__half*)(smraw + FG_XS);       // stride 72
    __half* W1s  = (__half*)(smraw + FG_W1S);      // stride 72
    __half* W2s  = (__half*)(smraw + FG_W2S);      // stride 136
    __half* C1s  = (__half*)(smraw + FG_C1S);      // stride 136
    __half* F2s  = (__half*)(smraw + FG_XS);       // stride 136 (overlays Xs+W1s)
    __half* Wb[2]; Wb[0] = W2s; Wb[1] = C1s;

    int tid = threadIdx.x;
    int net = blockIdx.y;
    size_t rowbase = (size_t)blockIdx.x * 128;

    const float* w1 = net ? c_w1 : a_w1;
    const float* b1 = net ? c_b1 : a_b1;
    const float* w2 = net ? c_w2 : a_w2;
    const float* b2 = net ? c_b2 : a_b2;
    const float* bih = net ? c_bih : a_bih;
    const float* bhh = net ? c_bhh : a_bhh;

    {   // X [128][64]
        const float4* xg = (const float4*)(x + rowbase * SS);
        for (int i = tid; i < 128 * 16; i += 256) {
            int r = i >> 4, c4 = i & 15;
            float4 v = xg[(size_t)r * 16 + c4];
            *(__half2*)&Xs[r * XS_STR + c4 * 4]     = __floats2half2_rn(v.x, v.y);
            *(__half2*)&Xs[r * XS_STR + c4 * 4 + 2] = __floats2half2_rn(v.z, v.w);
        }
    }
    {   // W1 [128][64]
        const float4* wg = (const float4*)w1;
        for (int i = tid; i < 128 * 16; i += 256) {
            int r = i >> 4, c4 = i & 15;
            float4 v = wg[(size_t)r * 16 + c4];
            *(__half2*)&W1s[r * XS_STR + c4 * 4]     = __floats2half2_rn(v.x, v.y);
            *(__half2*)&W1s[r * XS_STR + c4 * 4 + 2] = __floats2half2_rn(v.z, v.w);
        }
    }
    {   // W2 [128][128]
        const float4* wg = (const float4*)w2;
        for (int i = tid; i < 128 * 32; i += 256) {
            int r = i >> 5, c4 = i & 31;
            float4 v = wg[(size_t)r * 32 + c4];
            *(__half2*)&W2s[r * MH_STR + c4 * 4]     = __floats2half2_rn(v.x, v.y);
            *(__half2*)&W2s[r * MH_STR + c4 * 4 + 2] = __floats2half2_rn(v.z, v.w);
        }
    }
    if (tid < 128) { bs1[tid] = __ldg(b1 + tid); bs2[tid] = __ldg(b2 + tid); }
    for (int i = tid; i < 512; i += 256) bsum[i] = __ldg(bih + i) + __ldg(bhh + i);
    __syncthreads();

    int wid = tid >> 5, lane = tid & 31;
    int warp_m = wid & 3, warp_n = wid >> 2;
    int m_base = warp_m * 32, n_base = warp_n * 64;

    float acc[2][8][4];

    // -------- stage A: C1 = relu(X @ W1.T + b1), K=64 --------
    #pragma unroll
    for (int mt = 0; mt < 2; mt++)
        #pragma unroll
        for (int nt = 0; nt < 8; nt++)
            #pragma unroll
            for (int q = 0; q < 4; q++) acc[mt][nt][q] = 0.f;

    #pragma unroll
    for (int kt = 0; kt < 4; kt++) {
        int k0 = kt * 16;
        unsigned a[2][4], b[8][2];
        #pragma unroll
        for (int mt = 0; mt < 2; mt++) {
            int r = m_base + mt * 16 + (lane & 15);
            int c = k0 + ((lane >> 4) << 3);
            ldsm4(a[mt], Xs + r * XS_STR + c);
        }
        #pragma unroll
        for (int np = 0; np < 4; np++) {
            int n0 = n_base + np * 16;
            int rr = n0 + ((lane >> 4) << 3) + (lane & 7);
            int cc = k0 + (((lane >> 3) & 1) << 3);
            unsigned t4[4];
            ldsm4(t4, W1s + rr * XS_STR + cc);
            b[np * 2][0] = t4[0]; b[np * 2][1] = t4[1];
            b[np * 2 + 1][0] = t4[2]; b[np * 2 + 1][1] = t4[3];
        }
        #pragma unroll
        for (int mt = 0; mt < 2; mt++)
            #pragma unroll
            for (int nt = 0; nt < 8; nt++)
                mma16816(acc[mt][nt], a[mt], b[nt]);
    }
    #pragma unroll
    for (int mt = 0; mt < 2; mt++) {
        #pragma unroll
        for (int nt = 0; nt < 8; nt++) {
            int r = m_base + mt * 16 + (lane >> 2);
            int c = n_base + nt * 8 + 2 * (lane & 3);
            float v0 = fmaxf(acc[mt][nt][0] + bs1[c], 0.f);
            float v1 = fmaxf(acc[mt][nt][1] + bs1[c + 1], 0.f);
            float v2 = fmaxf(acc[mt][nt][2] + bs1[c], 0.f);
            float v3 = fmaxf(acc[mt][nt][3] + bs1[c + 1], 0.f);
            *(__half2*)&C1s[r * MH_STR + c]       = __floats2half2_rn(v0, v1);
            *(__half2*)&C1s[(r + 8) * MH_STR + c] = __floats2half2_rn(v2, v3);
        }
    }
    __syncthreads();

    // -------- stage B: F2 = relu(C1 @ W2.T + b2), K=128 --------
    #pragma unroll
    for (int mt = 0; mt < 2; mt++)
        #pragma unroll
        for (int nt = 0; nt < 8; nt++)
            #pragma unroll
            for (int q = 0; q < 4; q++) acc[mt][nt][q] = 0.f;

    #pragma unroll
    for (int kt = 0; kt < 8; kt++) {
        int k0 = kt * 16;
        unsigned a[2][4], b[8][2];
        #pragma unroll
        for (int mt = 0; mt < 2; mt++) {
            int r = m_base + mt * 16 + (lane & 15);
            int c = k0 + ((lane >> 4) << 3);
            ldsm4(a[mt], C1s + r * MH_STR + c);
        }
        #pragma unroll
        for (int np = 0; np < 4; np++) {
            int n0 = n_base + np * 16;
            int rr = n0 + ((lane >> 4) << 3) + (lane & 7);
            int cc = k0 + (((lane >> 3) & 1) << 3);
            unsigned t4[4];
            ldsm4(t4, W2s + rr * MH_STR + cc);
            b[np * 2][0] = t4[0]; b[np * 2][1] = t4[1];
            b[np * 2 + 1][0] = t4[2]; b[np * 2 + 1][1] = t4[3];
        }
        #pragma unroll
        for (int mt = 0; mt < 2; mt++)
            #pragma unroll
            for (int nt = 0; nt < 8; nt++)
                mma16816(acc[mt][nt], a[mt], b[nt]);
    }
    // epilogue B -> F2s
    #pragma unroll
    for (int mt = 0; mt < 2; mt++) {
        #pragma unroll
        for (int nt = 0; nt < 8; nt++) {
            int r = m_base + mt * 16 + (lane >> 2);
            int c = n_base + nt * 8 + 2 * (lane & 3);
            float v0 = fmaxf(acc[mt][nt][0] + bs2[c], 0.f);
            float v1 = fmaxf(acc[mt][nt][1] + bs2[c + 1], 0.f);
            float v2 = fmaxf(acc[mt][nt][2] + bs2[c], 0.f);
            float v3 = fmaxf(acc[mt][nt][3] + bs2[c + 1], 0.f);
            *(__half2*)&F2s[r * MH_STR + c]       = __floats2half2_rn(v0, v1);
            *(__half2*)&F2s[(r + 8) * MH_STR + c] = __floats2half2_rn(v2, v3);
        }
    }
    __syncthreads();

    // -------- gx phase: loop 4 weight chunks; A re-ldsm'd from F2s --------
    const __half* wsrc = g_wih16 + (size_t)net * 65536;

    for (int i = tid; i < 2048; i += 256) {
        int r = i >> 4, c = i & 15;
        cpa16(Wb[0] + r * MH_STR + c * 8, wsrc + r * 128 + c * 8);
    }
    CP_COMMIT;
    CP_WAIT0;
    __syncthreads();

    __half* outp = g_gxh + (size_t)net * NROW * 512;

    #pragma unroll
    for (int ch = 0; ch < 4; ch++) {
        if (ch < 3) {
            const __half* src = wsrc + (ch + 1) * 128 * 128;
            __half* dst = Wb[(ch + 1) & 1];
            for (int i = tid; i < 2048; i += 256) {
                int r = i >> 4, c = i & 15;
                cpa16(dst + r * MH_STR + c * 8, src + r * 128 + c * 8);
            }
            CP_COMMIT;
        }
        const __half* Ws = Wb[ch & 1];

        #pragma unroll
        for (int mt = 0; mt < 2; mt++)
            #pragma unroll
            for (int nt = 0; nt < 8; nt++)
                #pragma unroll
                for (int q = 0; q < 4; q++) acc[mt][nt][q] = 0.f;

        #pragma unroll
        for (int kt = 0; kt < 8; kt++) {
            int k0 = kt * 16;
            unsigned a[2][4], b[8][2];
            #pragma unroll
            for (int mt = 0; mt < 2; mt++) {
                int r = m_base + mt * 16 + (lane & 15);
                int c = k0 + ((lane >> 4) << 3);
                ldsm4(a[mt], F2s + r * MH_STR + c);
            }
            #pragma unroll
            for (int np = 0; np < 4; np++) {
                int n0 = n_base + np * 16;
                int rr = n0 + ((lane >> 4) << 3) + (lane & 7);
                int cc = k0 + (((lane >> 3) & 1) << 3);
                unsigned t4[4];
                ldsm4(t4, Ws + rr * MH_STR + cc);
                b[np * 2][0] = t4[0]; b[np * 2][1] = t4[1];
                b[np * 2 + 1][0] = t4[2]; b[np * 2 + 1][1] = t4[3];
            }
            #pragma unroll
            for (int mt = 0; mt < 2; mt++)
                #pragma unroll
                for (int nt = 0; nt < 8; nt++)
                    mma16816(acc[mt][nt], a[mt], b[nt]);
        }
        #pragma unroll
        for (int mt = 0; mt < 2; mt++) {
            #pragma unroll
            for (int nt = 0; nt < 8; nt++) {
                int r = m_base + mt * 16 + (lane >> 2);
                int c = n_base + nt * 8 + 2 * (lane & 3);
                int gc = ch * 128 + c;
                float v0 = acc[mt][nt][0] + bsum[gc];
                float v1 = acc[mt][nt][1] + bsum[gc + 1];
                float v2 = acc[mt][nt][2] + bsum[gc];
                float v3 = acc[mt][nt][3] + bsum[gc + 1];
                *(__half2*)(outp + (rowbase + r) * (size_t)512 + gc) = __floats2half2_rn(v0, v1);
                *(__half2*)(outp + (rowbase + r + 8) * (size_t)512 + gc) = __floats2half2_rn(v2, v3);
            }
        }
        if (ch < 3) {
            CP_WAIT0;
            __syncthreads();
        }
    }
}

// =====================================================================
// LSTM recurrence, TRANSPOSED formulation (R15), cluster-pair j-split.
// CHANGE vs R15: warp-elected release-arrive. Each thread pushes its b32
// DSMEM data, then __syncwarp() orders all lanes' pushes before lane 0's
// single cumulative release-arrive. Barrier arrive count 256 -> 8.
// Eliminates the per-step 256-way mbarrier RMW serialization.
// smem (bytes):
//   Ws   [256][136] half  0     .. 69632
//   hbuf [2][8][136] half 69632 .. 73984
//   gxs  [2][8][264] half 73984 .. 82432
//   maskb[512] u32        82432 .. 84480
//   mbars[2] u64          84480 .. 84496
// =====================================================================
#define LW_WS  0
#define LW_HB  69632
#define LW_GX  73984
#define LW_MB  82432
#define LW_BAR 84480
#define LSTM_SMEM 84512

__global__ void __launch_bounds__(256) __cluster_dims__(2, 1, 1)
lstm_cluster_kernel(const int* __restrict__ dones,
                    const float* __restrict__ a_whh, const float* __restrict__ c_whh)
{
    extern __shared__ __align__(16) char sm[];
    __half*   Ws    = (__half*)(sm + LW_WS);
    __half*   hbuf  = (__half*)(sm + LW_HB);
    __half*   gxs   = (__half*)(sm + LW_GX);
    unsigned* maskb = (unsigned*)(sm + LW_MB);

    int tid = threadIdx.x;
    int bx  = blockIdx.x;
    int net = bx >> 6;
    int rowgroup = (bx >> 1) & 31;
    int rb = rowgroup << 3;                       // first of 8 batch rows
    unsigned rank;
    asm("mov.u32 %0, %%cluster_ctarank;" : "=r"(rank));
    unsigned peer = rank ^ 1u;
    int jbase = (int)rank * 64;
    const float* whh = net ? c_whh : a_whh;

    // ---- permuted Wp rows: m -> w=m>>5, offs=m&31, gate=offs>>3, jl=8w+(offs&7) ----
    for (int i = tid; i < 256 * 32; i += 256) {
        int m = i >> 5, c4 = i & 31;
        int w  = m >> 5;
        int offs = m & 31;
        int g  = offs >> 3;
        int jl = (w << 3) + (offs & 7);
        int orig = g * 128 + jbase + jl;
        float4 v = ((const float4*)whh)[orig * 32 + c4];
        *(__half2*)&Ws[m * 136 + c4 * 4]     = __floats2half2_rn(v.x, v.y);
        *(__half2*)&Ws[m * 136 + c4 * 4 + 2] = __floats2half2_rn(v.z, v.w);
    }
    for (int i = tid; i < 2 * 8 * 136; i += 256) hbuf[i] = __float2half(0.f);
    for (int s = tid; s < 512; s += 256) {
        unsigned b = 0;
        #pragma unroll
        for (int r = 0; r < 8; r++) b |= ((unsigned)dones[s * 256 + rb + r] & 1u) << r;
        maskb[s] = b;
    }
    const __half* gxg = g_gxh + (size_t)net * NROW * 512;
    {   // gx(0): gxs[row][seg*64+u] = gx[row][seg*128 + jbase + u]
        int row = tid >> 5, rem = tid & 31, seg = rem >> 3, q = rem & 7;
        uint4 v = *(const uint4*)(gxg + (size_t)(rb + row) * 512 + seg * 128 + jbase + q * 8);
        ((uint4*)gxs)[33 * row + 8 * seg + q] = v;
    }
    unsigned barL0 = smem_u32(sm + LW_BAR);
    unsigned barL1 = barL0 + 8;
    if (tid == 0) {
        asm volatile("mbarrier.init.shared.b64 [%0], %1;" :: "r"(barL0), "r"(8u));
        asm volatile("mbarrier.init.shared.b64 [%0], %1;" :: "r"(barL1), "r"(8u));
    }
    __syncthreads();
    asm volatile("barrier.cluster.arrive.aligned;" ::: "memory");
    asm volatile("barrier.cluster.wait.aligned;" ::: "memory");

    unsigned remBar[2];
    remBar[0] = mapa_u32(barL0, peer);
    remBar[1] = mapa_u32(barL1, peer);

    int lane = tid & 31, wid = tid >> 5;

    // hoist Wp A fragments: 2 mtiles x 8 kt x 4 regs (m rows [32w, 32w+32))
    unsigned afr[2][8][4];
    #pragma unroll
    for (int mt = 0; mt < 2; mt++)
        #pragma unroll
        for (int kt = 0; kt < 8; kt++) {
            int r = 32 * wid + mt * 16 + (lane & 15);
            int c = kt * 16 + ((lane >> 4) << 3);
            ldsm4(afr[mt][kt], Ws + r * 136 + c);
        }

    int s  = lane >> 2;            // 0..7
    int jl = 8 * wid + s;          // this thread's local hidden col
    int bA = 2 * (lane & 3);       // batch rows
    int bB = bA + 1;
    bool leftT = ((s & 1) == 0);   // pair role: left stores row bA, right row bB
    int rowSt = leftT ? bA : bB;
    int colSt = leftT ? jl : (jl - 1);   // even in both cases -> 4B aligned

    // remote b32 push addresses for both hbuf ping-pong buffers
    unsigned remH[2];
    {
        unsigned base = smem_u32(hbuf);
        #pragma unroll
        for (int buf = 0; buf < 2; buf++)
            remH[buf] = mapa_u32(base + (unsigned)(((buf * 8 + rowSt) * 136 + jbase + colSt) * 2), peer);
    }

    float cstA = 0.f, cstB = 0.f;
    __half* hog = g_hh + (size_t)net * NROW * HH;
    int ph0 = 0, ph1 = 0;

    for (int t = 0; t < TT; t++) {
        bool haveNext = (t < TT - 1);
        uint4 pf;
        if (haveNext) {
            int prow = tid >> 5, rem = tid & 31, seg = rem >> 3, q = rem & 7;
            pf = *(const uint4*)(gxg + (size_t)((t + 1) * 256 + rb + prow) * 512
                                 + seg * 128 + jbase + q * 8);
        }
        if (t > 0) {
            if ((t - 1) & 1) { mbar_wait_acq_cluster(barL1, (unsigned)ph1); ph1 ^= 1; }
            else             { mbar_wait_acq_cluster(barL0, (unsigned)ph0); ph0 ^= 1; }
        }

        // B fragments from h (8 batch rows x 128 cols), shared by both mtiles
        const __half* hb = hbuf + (t & 1) * (8 * 136);
        unsigned B[8][2];
        #pragma unroll
        for (int kt = 0; kt < 8; kt++)
            ldsm2(B[kt], hb + (lane & 7) * 136 + kt * 16 + (((lane >> 3) & 1) << 3));

        float acc[2][4];
        #pragma unroll
        for (int mt = 0; mt < 2; mt++)
            #pragma unroll
            for (int q = 0; q < 4; q++) acc[mt][q] = 0.f;

        #pragma unroll
        for (int kt = 0; kt < 8; kt++) {
            mma16816(acc[0], afr[0][kt], B[kt]);
            mma16816(acc[1], afr[1][kt], B[kt]);
        }
        // acc[0][0/1] = gate i (bA/bB); acc[0][2/3] = gate f;
        // acc[1][0/1] = gate g;         acc[1][2/3] = gate o.

        // ---- register epilogue (pair-shuffle b32 stores) ----
        {
            const __half* gxcur = gxs + (t & 1) * 2112;
            float giA = __half2float(gxcur[bA * 264 + jl]);
            float giB = __half2float(gxcur[bB * 264 + jl]);
            float gfA = __half2float(gxcur[bA * 264 + 64 + jl]);
            float gfB = __half2float(gxcur[bB * 264 + 64 + jl]);
            float ggA = __half2float(gxcur[bA * 264 + 128 + jl]);
            float ggB = __half2float(gxcur[bB * 264 + 128 + jl]);
            float goA = __half2float(gxcur[bA * 264 + 192 + jl]);
            float goB = __half2float(gxcur[bB * 264 + 192 + jl]);

            float iA = sig_t(acc[0][0] + giA), iB = sig_t(acc[0][1] + giB);
            float fA = sig_t(acc[0][2] + gfA), fB = sig_t(acc[0][3] + gfB);
            float gA = tanh_t(acc[1][0] + ggA), gB = tanh_t(acc[1][1] + ggB);
            float oA = sig_t(acc[1][2] + goA), oB = sig_t(acc[1][3] + goB);

            float c2A = fA * cstA + iA * gA;
            float c2B = fB * cstB + iB * gB;
            float h2A = oA * tanh_t(c2A);
            float h2B = oB * tanh_t(c2B);

            unsigned bits = maskb[t];
            float mA = ((bits >> bA) & 1u) ? 0.f : 1.f;
            float mB = ((bits >> bB) & 1u) ? 0.f : 1.f;
            cstA = c2A * mA;
            cstB = c2B * mB;

            // pack {rowA, rowB} halves; exchange with jl-neighbor (lane^4)
            unsigned pkm = (unsigned)__half_as_ushort(__float2half(h2A * mA))
                         | ((unsigned)__half_as_ushort(__float2half(h2B * mB)) << 16);
            unsigned pku = (unsigned)__half_as_ushort(__float2half(h2A))
                         | ((unsigned)__half_as_ushort(__float2half(h2B)) << 16);
            unsigned otm = __shfl_xor_sync(0xffffffffu, pkm, 4);
            unsigned otu = __shfl_xor_sync(0xffffffffu, pku, 4);
            // left: row bA cols {jl, jl+1}; right: row bB cols {jl-1, jl}
            unsigned vm = leftT ? ((pkm & 0xFFFFu) | (otm << 16))
                                : ((otm >> 16) | (pkm & 0xFFFF0000u));
            unsigned vu = leftT ? ((pku & 0xFFFFu) | (otu << 16))
                                : ((otu >> 16) | (pku & 0xFFFF0000u));

            if (haveNext) {
                int nb = (t + 1) & 1;
                // remote b32 push ASAP (in flight during rest of epilogue)
                st_cluster_u32(remH[nb], vm);
                // warp-level HB for all lanes' pushes, then ONE cumulative
                // release-arrive per warp (barrier count = 8)
                __syncwarp();
                if (lane == 0) mbar_arrive_rel_cluster(remBar[t & 1]);
                // local store (same layout)
                *(unsigned*)&hbuf[(nb * 8 + rowSt) * 136 + jbase + colSt] = vm;
                {
                    int prow = tid >> 5, rem = tid & 31, seg = rem >> 3, q = rem & 7;
                    ((uint4*)(gxs + nb * 2112))[33 * prow + 8 * seg + q] = pf;
                }
            }
            *(unsigned*)(hog + (size_t)(t * 256 + rb + rowSt) * HH + jbase + colSt) = vu;
        }
        __syncthreads();
    }

    asm volatile("barrier.cluster.arrive.aligned;" ::: "memory");
    asm volatile("barrier.cluster.wait.aligned;" ::: "memory");
}

// =====================================================================
// Heads on HMMA (exact R8)
// =====================================================================
#define HD_HA 0
#define HD_HC 34816
#define HD_W  69632
#define HD_B  78336
#define HD_SMEM 78464

__global__ void __launch_bounds__(256) heads_mma_kernel(
    const float* __restrict__ mw, const float* __restrict__ mb,
    const float* __restrict__ lw, const float* __restrict__ lb,
    const float* __restrict__ vw, const float* __restrict__ vb,
    float* __restrict__ out)
{
    extern __shared__ __align__(16) char sm[];
    __half* Ha = (__half*)(sm + HD_HA);   // [128][136]
    __half* Hc = (__half*)(sm + HD_HC);   // [128][136]
    __half* Wh = (__half*)(sm + HD_W);    // [32][136]
    float*  bsm = (float*)(sm + HD_B);

    int tid = threadIdx.x;
    size_t rowbase = (size_t)blockIdx.x * 128;

    const __half* ha = g_hh + rowbase * HH;
    const __half* hc = g_hh + (size_t)NROW * HH + rowbase * HH;
    for (int i = tid; i < 2048; i += 256) {
        int r = i >> 4, c = i & 15;
        cpa16(Ha + r * 136 + c * 8, ha + (size_t)r * HH + c * 8);
        cpa16(Hc + r * 136 + c * 8, hc + (size_t)r * HH + c * 8);
    }
    CP_COMMIT;
    for (int i = tid; i < 4096; i += 256) {
        int r = i >> 7, c = i & 127;
        float v = 0.f;
        if (r < 8) v = mw[r * 128 + c];
        else if (r < 16) v = lw[(r - 8) * 128 + c];
        else if (r == 16) v = vw[c];
        Wh[r * 136 + c] = __float2half(v);
    }
    if (tid < 8) { bsm[tid] = mb[tid]; bsm[8 + tid] = lb[tid]; }
    if (tid == 16) bsm[16] = vb[0];
    CP_WAIT0;
    __syncthreads();

    int wid = tid >> 5, lane = tid & 31;
    int r0 = wid * 16;

    unsigned bf[8][3][2];
    #pragma unroll
    for (int kt = 0; kt < 8; kt++) {
        int k0 = kt * 16;
        {
            int rr = ((lane >> 4) << 3) + (lane & 7);
            int cc = k0 + (((lane >> 3) & 1) << 3);
            unsigned t4[4];
            ldsm4(t4, Wh + rr * 136 + cc);
            bf[kt][0][0] = t4[0]; bf[kt][0][1] = t4[1];
            bf[kt][1][0] = t4[2]; bf[kt][1][1] = t4[3];
        }
        {
            int rr = 16 + ((lane >> 4) << 3) + (lane & 7);
            int cc = k0 + (((lane >> 3) & 1) << 3);
            unsigned t4[4];
            ldsm4(t4, Wh + rr * 136 + cc);
            bf[kt][2][0] = t4[0]; bf[kt][2][1] = t4[1];
        }
    }

    float accM[4], accL[4], accV[4];
    #pragma unroll
    for (int q = 0; q < 4; q++) { accM[q] = 0.f; accL[q] = 0.f; accV[q] = 0.f; }

    #pragma unroll
    for (int kt = 0; kt < 8; kt++) {
        int k0 = kt * 16;
        unsigned a[4], cfr[4];
        ldsm4(a,   Ha + (r0 + (lane & 15)) * 136 + k0 + ((lane >> 4) << 3));
        ldsm4(cfr, Hc + (r0 + (lane & 15)) * 136 + k0 + ((lane >> 4) << 3));
        mma16816(accM, a, bf[kt][0]);
        mma16816(accL, a, bf[kt][1]);
        mma16816(accV, cfr, bf[kt][2]);
    }

    int row = lane >> 2, c0 = 2 * (lane & 3);
    size_t gr0 = rowbase + r0 + row;
    size_t gr1 = gr0 + 8;
    *(float2*)(out + gr0 * 8 + c0) = make_float2(accM[0] + bsm[c0], accM[1] + bsm[c0 + 1]);
    *(float2*)(out + gr1 * 8 + c0) = make_float2(accM[2] + bsm[c0], accM[3] + bsm[c0 + 1]);
    float* outs = out + (size_t)NROW * 8;
    *(float2*)(outs + gr0 * 8 + c0) =
        make_float2(__expf(accL[0] + bsm[8 + c0]), __expf(accL[1] + bsm[8 + c0 + 1]));
    *(float2*)(outs + gr1 * 8 + c0) =
        make_float2(__expf(accL[2] + bsm[8 + c0]), __expf(accL[3] + bsm[8 + c0 + 1]));
    if ((lane & 3) == 0) {
        float* outv = out + (size_t)NROW * 16;
        outv[gr0] = accV[0] + bsm[16];
        outv[gr1] = accV[2] + bsm[16];
    }
}

// ---------------- launch ----------------
extern "C" void kernel_launch(void* const* d_in, const int* in_sizes, int n_in,
                              void* d_out, int out_size)
{
    const float* state  = (const float*)d_in[0];
    const int*   dones  = (const int*)d_in[1];
    const float* a_w1   = (const float*)d_in[2];
    const float* a_b1   = (const float*)d_in[3];
    const float* a_w2   = (const float*)d_in[4];
    const float* a_b2   = (const float*)d_in[5];
    const float* c_w1   = (const float*)d_in[6];
    const float* c_b1   = (const float*)d_in[7];
    const float* c_w2   = (const float*)d_in[8];
    const float* c_b2   = (const float*)d_in[9];
    const float* a_wih  = (const float*)d_in[10];
    const float* a_whh  = (const float*)d_in[11];
    const float* a_bih  = (const float*)d_in[12];
    const float* a_bhh  = (const float*)d_in[13];
    const float* c_wih  = (const float*)d_in[14];
    const float* c_whh  = (const float*)d_in[15];
    const float* c_bih  = (const float*)d_in[16];
    const float* c_bhh  = (const float*)d_in[17];
    const float* mean_w = (const float*)d_in[18];
    const float* mean_b = (const float*)d_in[19];
    const float* lstd_w = (const float*)d_in[20];
    const float* lstd_b = (const float*)d_in[21];
    const float* val_w  = (const float*)d_in[22];
    const float* val_b  = (const float*)d_in[23];

    cudaFuncSetAttribute(fg_kernel, cudaFuncAttributeMaxDynamicSharedMemorySize, FG_SMEM);
    cudaFuncSetAttribute(lstm_cluster_kernel, cudaFuncAttributeMaxDynamicSharedMemorySize, LSTM_SMEM);
    cudaFuncSetAttribute(heads_mma_kernel, cudaFuncAttributeMaxDynamicSharedMemorySize, HD_SMEM);

    pack16_kernel<<<512, 256>>>(a_wih, c_wih);

    dim3 fgg(1024, 2);
    fg_kernel<<<fgg, 256, FG_SMEM>>>(state,
                                     a_w1, a_b1, a_w2, a_b2,
                                     c_w1, c_b1, c_w2, c_b2,
                                     a_bih, a_bhh, c_bih, c_bhh);

    lstm_cluster_kernel<<<128, 256, LSTM_SMEM>>>(dones, a_whh, c_whh);

    heads_mma_kernel<<<1024, 256, HD_SMEM>>>(mean_w, mean_b, lstd_w, lstd_b,
                                             val_w, val_b, (float*)d_out);
}